// round 2
// baseline (speedup 1.0000x reference)
#include <cuda_runtime.h>
#include <cuda_bf16.h>
#include <cstdint>

#define NPTS 8192
#define DIM  512

// ---------------- device scratch (no allocations allowed) ----------------
__device__ float g_sq[NPTS];
__device__ float g_pmin[4 * NPTS];
__device__ int   g_pidx[4 * NPTS];
__device__ int   g_closest[NPTS];

typedef unsigned long long u64;

__device__ __forceinline__ u64 pack2(float x, float y) {
    u64 r;
    asm("mov.b64 %0, {%1, %2};" : "=l"(r) : "r"(__float_as_uint(x)), "r"(__float_as_uint(y)));
    return r;
}
__device__ __forceinline__ u64 fma2(u64 a, u64 b, u64 c) {
    u64 d;
    asm("fma.rn.f32x2 %0, %1, %2, %3;" : "=l"(d) : "l"(a), "l"(b), "l"(c));
    return d;
}
__device__ __forceinline__ float2 unpack2(u64 p) {
    unsigned lo, hi;
    asm("mov.b64 {%0, %1}, %2;" : "=r"(lo), "=r"(hi) : "l"(p));
    float2 f;
    f.x = __uint_as_float(lo);
    f.y = __uint_as_float(hi);
    return f;
}

// ---------------- kernel 1: row squared norms ----------------
__global__ void row_norms_kernel(const float* __restrict__ xs) {
    int warp = threadIdx.x >> 5, lane = threadIdx.x & 31;
    int row = blockIdx.x * 8 + warp;
    const float* p = xs + (size_t)row * DIM;
    float s = 0.f;
#pragma unroll
    for (int t = 0; t < 16; t++) {
        float v = p[lane + 32 * t];
        s += v * v;
    }
#pragma unroll
    for (int off = 16; off; off >>= 1) s += __shfl_xor_sync(0xffffffffu, s, off);
    if (lane == 0) g_sq[row] = s;
}

// ---------------- kernel 2: fused Gram + argmin (fp32x2 SGEMM) ----------------
// 128x128 output tiles, BK=16, 256 threads, 8x8 per thread (4x f32x2 pairs).
// Grid: (64 row tiles, 4 column splits). Each block sweeps 16 column subtiles,
// keeping a per-thread running argmin per row, then reduces across the 16
// threads sharing each row.
#define BM 128
#define BN 128
#define BK 16
#define SMP 132  // padded stride (132 % 4 == 0 keeps float4 alignment)

__global__ __launch_bounds__(256, 2) void dist_argmin_kernel(const float* __restrict__ xs) {
    __shared__ float As[BK][SMP];
    __shared__ float Bs[BK][SMP];
    __shared__ float rv[256 * 8];
    __shared__ int   ri[256 * 8];

    const int tid = threadIdx.x;
    const int tx = tid & 15;        // 0..15 -> column group
    const int ty = tid >> 4;        // 0..15 -> row group
    const int row0 = blockIdx.x * BM;
    const int colbase = blockIdx.y * (NPTS / 4);

    float bestv[8];
    int   besti[8];
#pragma unroll
    for (int m = 0; m < 8; m++) { bestv[m] = 1e30f; besti[m] = 0; }

    for (int sub = 0; sub < 16; sub++) {
        const int col0 = colbase + sub * BN;

        u64 acc2[8][4];
#pragma unroll
        for (int m = 0; m < 8; m++)
#pragma unroll
            for (int n2 = 0; n2 < 4; n2++) acc2[m][n2] = 0ull;

        for (int kb = 0; kb < DIM; kb += BK) {
            // stage 128x16 A and B tiles (transposed) — 2 float4 per thread each
#pragma unroll
            for (int l = 0; l < 2; l++) {
                int e = tid + l * 256;
                int r = e >> 2;
                int k4 = (e & 3) * 4;
                float4 va = *(const float4*)&xs[(size_t)(row0 + r) * DIM + kb + k4];
                As[k4 + 0][r] = va.x; As[k4 + 1][r] = va.y;
                As[k4 + 2][r] = va.z; As[k4 + 3][r] = va.w;
                float4 vb = *(const float4*)&xs[(size_t)(col0 + r) * DIM + kb + k4];
                Bs[k4 + 0][r] = vb.x; Bs[k4 + 1][r] = vb.y;
                Bs[k4 + 2][r] = vb.z; Bs[k4 + 3][r] = vb.w;
            }
            __syncthreads();

#pragma unroll
            for (int k = 0; k < BK; k++) {
                float a[8];
                const float4* ap = (const float4*)&As[k][ty * 8];
                float4 a0 = ap[0], a1 = ap[1];
                a[0] = a0.x; a[1] = a0.y; a[2] = a0.z; a[3] = a0.w;
                a[4] = a1.x; a[5] = a1.y; a[6] = a1.z; a[7] = a1.w;
                u64 b2[4];
                const u64* bp = (const u64*)&Bs[k][tx * 8];
                b2[0] = bp[0]; b2[1] = bp[1]; b2[2] = bp[2]; b2[3] = bp[3];
#pragma unroll
                for (int m = 0; m < 8; m++) {
                    u64 a2 = pack2(a[m], a[m]);
#pragma unroll
                    for (int n2 = 0; n2 < 4; n2++)
                        acc2[m][n2] = fma2(a2, b2[n2], acc2[m][n2]);
                }
            }
            __syncthreads();
        }

        // epilogue: distance (sq_j - 2*dot; sq_i is a per-row constant) + argmin
#pragma unroll
        for (int n2 = 0; n2 < 4; n2++) {
            int c0 = col0 + tx * 8 + 2 * n2;
            float sq0 = g_sq[c0];
            float sq1 = g_sq[c0 + 1];
#pragma unroll
            for (int m = 0; m < 8; m++) {
                int r = row0 + ty * 8 + m;
                float2 v = unpack2(acc2[m][n2]);
                float d0 = sq0 - 2.f * v.x;
                float d1 = sq1 - 2.f * v.y;
                if (c0 != r && d0 < bestv[m]) { bestv[m] = d0; besti[m] = c0; }
                if (c0 + 1 != r && d1 < bestv[m]) { bestv[m] = d1; besti[m] = c0 + 1; }
            }
        }
    }

    // cross-thread (tx) reduction per row
#pragma unroll
    for (int m = 0; m < 8; m++) { rv[tid * 8 + m] = bestv[m]; ri[tid * 8 + m] = besti[m]; }
    __syncthreads();
    if (tx == 0) {
        for (int m = 0; m < 8; m++) {
            float bv = rv[tid * 8 + m];
            int bi = ri[tid * 8 + m];
            for (int t = 1; t < 16; t++) {
                float v = rv[(tid + t) * 8 + m];
                int id2 = ri[(tid + t) * 8 + m];
                if (v < bv || (v == bv && id2 < bi)) { bv = v; bi = id2; }
            }
            int row = row0 + ty * 8 + m;
            g_pmin[blockIdx.y * NPTS + row] = bv;
            g_pidx[blockIdx.y * NPTS + row] = bi;
        }
    }
}

// ---------------- kernel 3: reduce the 4 column-split partial argmins ----------------
__global__ void reduce_argmin_kernel() {
    int i = blockIdx.x * 256 + threadIdx.x;
    if (i >= NPTS) return;
    float bv = 1e30f;
    int bi = 0;
    for (int s = 0; s < 4; s++) {
        float v = g_pmin[s * NPTS + i];
        if (v < bv) { bv = v; bi = g_pidx[s * NPTS + i]; }
    }
    g_closest[i] = bi;
}

// ---------------- kernel 4: fused Taylor-encoder + decoder (one warp per row) ----------------
// JVP identity: z = W3(m2 o (W2(m1 o (W1 x + b1)) + b2)) + b3 with masks m1,m2
// from the x0 forward pass.
#define MLP_SMEM_FLOATS (32768 + 2048 + 1024 + 1024 + 2048 + 8 * 320)

__global__ __launch_bounds__(256, 1) void mlp_kernel(
    const float* __restrict__ xs,
    const float* __restrict__ W1, const float* __restrict__ b1,
    const float* __restrict__ W2, const float* __restrict__ b2,
    const float* __restrict__ W3, const float* __restrict__ b3,
    const float* __restrict__ D1, const float* __restrict__ d1,
    const float* __restrict__ D2, const float* __restrict__ d2,
    const float* __restrict__ D3, const float* __restrict__ d3,
    float* __restrict__ out) {
    extern __shared__ float smem[];
    float* sD3t = smem;               // [64][512] transposed D3
    float* sW2t = sD3t + 32768;       // [64][32]
    float* sW3t = sW2t + 2048;        // [32][32]
    float* sD1t = sW3t + 1024;        // [32][32]
    float* sD2t = sD1t + 1024;        // [32][64]
    float* sScr = sD2t + 2048;        // 8 warps * 320

    const int tid = threadIdx.x;
    for (int i = tid; i < 512 * 64; i += 256) { int dd = i >> 6, k = i & 63; sD3t[k * 512 + dd] = D3[i]; }
    for (int i = tid; i < 32 * 64; i += 256)  { int o = i >> 6, k = i & 63; sW2t[k * 32 + o] = W2[i]; }
    for (int i = tid; i < 32 * 32; i += 256)  { int o = i >> 5, k = i & 31; sW3t[k * 32 + o] = W3[i]; sD1t[k * 32 + o] = D1[i]; }
    for (int i = tid; i < 64 * 32; i += 256)  { int o = i >> 5, k = i & 31; sD2t[k * 64 + o] = D2[i]; }
    __syncthreads();

    const int warp = tid >> 5, lane = tid & 31;
    const int row = blockIdx.x * 8 + warp;
    float* scr = sScr + warp * 320;
    float* su  = scr;        // u1 -> a1u (64)
    float* sv  = scr + 64;   // v1 -> a1v (64)
    float* sa2 = scr + 128;  // (32)
    float* szs = scr + 160;  // (32)
    float* sh1 = scr + 192;  // (32)
    float* sh2 = scr + 224;  // (64)

    const int j = g_closest[row];
    const float* xp  = xs + (size_t)row * DIM;
    const float* x0p = xs + (size_t)j * DIM;
    float xr[16], x0r[16];
#pragma unroll
    for (int t = 0; t < 16; t++) { xr[t] = xp[lane + 32 * t]; x0r[t] = x0p[lane + 32 * t]; }

    // layer 1: 64 outputs, coalesced W1 reads, warp-shuffle reduce of both streams
    for (int o = 0; o < 64; o++) {
        const float* wp = W1 + o * DIM;
        float du = 0.f, dv = 0.f;
#pragma unroll
        for (int t = 0; t < 16; t++) {
            float w = __ldg(&wp[lane + 32 * t]);
            du += w * xr[t];
            dv += w * x0r[t];
        }
#pragma unroll
        for (int off = 16; off; off >>= 1) {
            du += __shfl_xor_sync(0xffffffffu, du, off);
            dv += __shfl_xor_sync(0xffffffffu, dv, off);
        }
        if (lane == 0) { float bb = __ldg(&b1[o]); su[o] = du + bb; sv[o] = dv + bb; }
    }
    __syncwarp();

    // relu mask from v-path
#pragma unroll
    for (int h = 0; h < 2; h++) {
        int k = lane + 32 * h;
        float v = sv[k], u = su[k];
        su[k] = (v > 0.f) ? u : 0.f;
        sv[k] = (v > 0.f) ? v : 0.f;
    }
    __syncwarp();

    // layer 2 (both streams), then layer 3 (masked u only)
    {
        int o = lane;
        float u2 = 0.f, v2 = 0.f;
#pragma unroll
        for (int k = 0; k < 64; k++) {
            float w = sW2t[k * 32 + o];
            u2 += w * su[k];
            v2 += w * sv[k];
        }
        float bb = __ldg(&b2[o]);
        u2 += bb; v2 += bb;
        sa2[o] = (v2 > 0.f) ? u2 : 0.f;
    }
    __syncwarp();
    {
        int o = lane;
        float z = __ldg(&b3[o]);
#pragma unroll
        for (int k = 0; k < 32; k++) z += sW3t[k * 32 + o] * sa2[k];
        szs[o] = z;
        out[(size_t)NPTS * DIM + (size_t)row * 32 + o] = z;  // zs output
    }
    __syncwarp();

    // decoder
    {
        int o = lane;
        float h = __ldg(&d1[o]);
#pragma unroll
        for (int k = 0; k < 32; k++) h += sD1t[k * 32 + o] * szs[k];
        sh1[o] = fmaxf(h, 0.f);
    }
    __syncwarp();
#pragma unroll
    for (int hh = 0; hh < 2; hh++) {
        int o = lane + 32 * hh;
        float h = __ldg(&d2[o]);
#pragma unroll
        for (int k = 0; k < 32; k++) h += sD2t[k * 64 + o] * sh1[k];
        sh2[o] = fmaxf(h, 0.f);
    }
    __syncwarp();

    // D3: 512 outputs per row, conflict-free transposed smem reads, coalesced stores
#pragma unroll 4
    for (int t = 0; t < 16; t++) {
        int dcol = lane + 32 * t;
        float acc = __ldg(&d3[dcol]);
#pragma unroll
        for (int k = 0; k < 64; k++) acc += sD3t[k * 512 + dcol] * sh2[k];
        out[(size_t)row * DIM + dcol] = acc;  // x_hats output
    }
}

// ---------------- launch ----------------
extern "C" void kernel_launch(void* const* d_in, const int* in_sizes, int n_in,
                              void* d_out, int out_size) {
    const float* xs = (const float*)d_in[0];
    const float* W1 = (const float*)d_in[1];
    const float* b1 = (const float*)d_in[2];
    const float* W2 = (const float*)d_in[3];
    const float* b2 = (const float*)d_in[4];
    const float* W3 = (const float*)d_in[5];
    const float* b3 = (const float*)d_in[6];
    const float* D1 = (const float*)d_in[7];
    const float* d1 = (const float*)d_in[8];
    const float* D2 = (const float*)d_in[9];
    const float* d2 = (const float*)d_in[10];
    const float* D3 = (const float*)d_in[11];
    const float* d3 = (const float*)d_in[12];
    float* out = (float*)d_out;

    row_norms_kernel<<<NPTS / 8, 256>>>(xs);

    dim3 g2(NPTS / BM, 4);
    dist_argmin_kernel<<<g2, 256>>>(xs);

    reduce_argmin_kernel<<<NPTS / 256, 256>>>();

    size_t smem_bytes = MLP_SMEM_FLOATS * sizeof(float);
    cudaFuncSetAttribute(mlp_kernel, cudaFuncAttributeMaxDynamicSharedMemorySize,
                         (int)smem_bytes);
    mlp_kernel<<<NPTS / 8, 256, smem_bytes>>>(xs, W1, b1, W2, b2, W3, b3,
                                              D1, d1, D2, d2, D3, d3, out);
}

// round 6
// speedup vs baseline: 1.8448x; 1.8448x over previous
#include <cuda_runtime.h>
#include <cuda_bf16.h>
#include <cstdint>

#define NPTS 8192
#define DIM  512
#define NBAND 64

// ---------------- device scratch (no allocations allowed) ----------------
__device__ float g_sq[NPTS];
__device__ float g_pmin[NBAND * NPTS];
__device__ int   g_pidx[NBAND * NPTS];
__device__ int   g_closest[NPTS];
__device__ __nv_bfloat16 g_xb[NPTS * 1024];  // per row: [hi(512) | lo(512)]

// ---------------- helpers ----------------
__device__ __forceinline__ uint32_t smem_u32(const void* p) {
    uint32_t a;
    asm("{ .reg .u64 t; cvta.to.shared.u64 t, %1; cvt.u32.u64 %0, t; }" : "=r"(a) : "l"(p));
    return a;
}
#define SWZ(b) ((b) ^ (((b) >> 3) & 0x70))

__device__ __forceinline__ void cp_async16(uint32_t dst, const void* src) {
    asm volatile("cp.async.cg.shared.global [%0], [%1], 16;" :: "r"(dst), "l"(src));
}

__device__ __forceinline__ void ldmatrix_x4(uint32_t* r, uint32_t addr) {
    asm volatile("ldmatrix.sync.aligned.m8n8.x4.shared.b16 {%0,%1,%2,%3}, [%4];"
                 : "=r"(r[0]), "=r"(r[1]), "=r"(r[2]), "=r"(r[3]) : "r"(addr));
}

__device__ __forceinline__ void mma16816(float* d, const uint32_t* a, uint32_t b0, uint32_t b1) {
    asm volatile(
        "mma.sync.aligned.m16n8k16.row.col.f32.bf16.bf16.f32 "
        "{%0,%1,%2,%3}, {%4,%5,%6,%7}, {%8,%9}, {%0,%1,%2,%3};"
        : "+f"(d[0]), "+f"(d[1]), "+f"(d[2]), "+f"(d[3])
        : "r"(a[0]), "r"(a[1]), "r"(a[2]), "r"(a[3]), "r"(b0), "r"(b1));
}

// ---------------- kernel 0: fp32 -> [hi|lo] bf16 split ----------------
__global__ void convert_kernel(const float* __restrict__ xs) {
    int i = blockIdx.x * 256 + threadIdx.x;  // over NPTS*DIM
    float x = xs[i];
    int row = i >> 9, col = i & 511;
    __nv_bfloat16 hi = __float2bfloat16(x);
    float lof = x - __bfloat162float(hi);
    g_xb[row * 1024 + col] = hi;
    g_xb[row * 1024 + 512 + col] = __float2bfloat16(lof);
}

// ---------------- kernel 1: row squared norms (fp32 exact) ----------------
__global__ void row_norms_kernel(const float* __restrict__ xs) {
    int warp = threadIdx.x >> 5, lane = threadIdx.x & 31;
    int row = blockIdx.x * 8 + warp;
    const float* p = xs + (size_t)row * DIM;
    float s = 0.f;
#pragma unroll
    for (int t = 0; t < 16; t++) {
        float v = p[lane + 32 * t];
        s += v * v;
    }
#pragma unroll
    for (int off = 16; off; off >>= 1) s += __shfl_xor_sync(0xffffffffu, s, off);
    if (lane == 0) g_sq[row] = s;
}

// ---------------- kernel 2: HMMA Gram + fused argmin ----------------
// CTA: 128x128 tile. 8 warps in 4x2 (warp_m x warp_n), warp tile 32x64.
// K = 1536 folded (hi.hi + hi.lo + lo.hi) as 24 chunks of 64 with source remap.
// 2-stage cp.async double buffer, SW128 software swizzle, ldmatrix + mma.sync.
#define TM 128
#define TN 128
#define KB 64
#define NCHUNK 24
#define A_BYTES (TM * 128)
#define B_BYTES (TN * 128)
#define STAGE_BYTES (A_BYTES + B_BYTES)
#define SM_SQ 0
#define SM_REDV 512
#define SM_REDI 1536
#define SM_TILE0 4096
#define SMEM_GEMM (SM_TILE0 + 2 * STAGE_BYTES)

__device__ __forceinline__ int a_koff(int c) {
    return (c < 16) ? (c & 7) * KB : 512 + (c - 16) * KB;
}
__device__ __forceinline__ int b_koff(int c) {
    return (c < 8) ? c * KB : (c < 16) ? 512 + (c - 8) * KB : (c - 16) * KB;
}

__global__ __launch_bounds__(256, 2) void gram_argmin_hmma() {
    extern __shared__ char smem[];
    const uint32_t sb = smem_u32(smem);
    float* sSq  = (float*)(smem + SM_SQ);
    float* redV = (float*)(smem + SM_REDV);
    int*   redI = (int*)(smem + SM_REDI);

    const int tid = threadIdx.x;
    const int lane = tid & 31, wid = tid >> 5;
    const int warp_m = wid & 3, warp_n = wid >> 2;
    const int row0 = blockIdx.x * TM;
    const int band = blockIdx.y;
    const int col0 = band * TN;

    if (tid < 128) sSq[tid] = g_sq[col0 + tid];

    float acc[2][8][4];
#pragma unroll
    for (int mf = 0; mf < 2; mf++)
#pragma unroll
        for (int nf = 0; nf < 8; nf++)
#pragma unroll
            for (int e = 0; e < 4; e++) acc[mf][nf][e] = 0.f;

    // per-thread staging assignment: 4 A segments + 4 B segments of 16B
    const int lr = tid >> 1;            // 0..127 row
    const int ls = (tid & 1) * 4;       // segment base 0 or 4

    // per-lane ldmatrix offsets (within A/B regions, pre-swizzled per kstep)
    const int lm_r = lane & 15;
    const int lm_k = (lane >> 4) * 8;

    // prologue: stage 0 <- chunk 0
    {
        const __nv_bfloat16* gA = g_xb + (size_t)row0 * 1024 + a_koff(0);
        const __nv_bfloat16* gB = g_xb + (size_t)col0 * 1024 + b_koff(0);
        uint32_t sa = sb + SM_TILE0, sbb = sa + A_BYTES;
#pragma unroll
        for (int it = 0; it < 4; it++) {
            int seg = ls + it;
            cp_async16(sa + SWZ(lr * 128 + seg * 16), gA + (size_t)lr * 1024 + seg * 8);
            cp_async16(sbb + SWZ(lr * 128 + seg * 16), gB + (size_t)lr * 1024 + seg * 8);
        }
        asm volatile("cp.async.commit_group;");
    }

    for (int c = 0; c < NCHUNK; c++) {
        const int cur = c & 1;
        if (c + 1 < NCHUNK) {
            const int nxt = cur ^ 1;
            const __nv_bfloat16* gA = g_xb + (size_t)row0 * 1024 + a_koff(c + 1);
            const __nv_bfloat16* gB = g_xb + (size_t)col0 * 1024 + b_koff(c + 1);
            uint32_t sa = sb + SM_TILE0 + nxt * STAGE_BYTES, sbb = sa + A_BYTES;
#pragma unroll
            for (int it = 0; it < 4; it++) {
                int seg = ls + it;
                cp_async16(sa + SWZ(lr * 128 + seg * 16), gA + (size_t)lr * 1024 + seg * 8);
                cp_async16(sbb + SWZ(lr * 128 + seg * 16), gB + (size_t)lr * 1024 + seg * 8);
            }
            asm volatile("cp.async.commit_group;");
            asm volatile("cp.async.wait_group 1;");
        } else {
            asm volatile("cp.async.wait_group 0;");
        }
        __syncthreads();

        const uint32_t Ab = sb + SM_TILE0 + cur * STAGE_BYTES;
        const uint32_t Bb = Ab + A_BYTES;
#pragma unroll
        for (int ks = 0; ks < 4; ks++) {
            const int k0 = ks * 16;
            uint32_t a[2][4];
#pragma unroll
            for (int mf = 0; mf < 2; mf++) {
                int r = warp_m * 32 + mf * 16 + lm_r;
                ldmatrix_x4(a[mf], Ab + SWZ(r * 128 + (k0 + lm_k) * 2));
            }
            uint32_t b[4][4];
#pragma unroll
            for (int p = 0; p < 4; p++) {
                int n = warp_n * 64 + p * 16 + lm_r;
                ldmatrix_x4(b[p], Bb + SWZ(n * 128 + (k0 + lm_k) * 2));
            }
#pragma unroll
            for (int mf = 0; mf < 2; mf++)
#pragma unroll
                for (int nf = 0; nf < 8; nf++)
                    mma16816(acc[mf][nf], a[mf], b[nf >> 1][nf & 1], b[nf >> 1][(nf & 1) + 2]);
        }
        __syncthreads();
    }

    // ---------- fused argmin epilogue ----------
    // acc[mf][nf][e]: rows ra = warp_m*32+mf*16+(lane>>2), rb = ra+8
    //                 cols      = warp_n*64+nf*8+(lane&3)*2 + (e&1)
    float bva[2], bvb[2];
    int   bia[2], bib[2];
#pragma unroll
    for (int mf = 0; mf < 2; mf++) { bva[mf] = 1e30f; bvb[mf] = 1e30f; bia[mf] = 0; bib[mf] = 0; }

#pragma unroll
    for (int mf = 0; mf < 2; mf++) {
        const int ra = row0 + warp_m * 32 + mf * 16 + (lane >> 2);
        const int rb = ra + 8;
#pragma unroll
        for (int nf = 0; nf < 8; nf++) {
            const int lc = warp_n * 64 + nf * 8 + (lane & 3) * 2;
            const float sq0 = sSq[lc], sq1 = sSq[lc + 1];
            const int c0 = col0 + lc;
            float d0 = sq0 - 2.f * acc[mf][nf][0];
            float d1 = sq1 - 2.f * acc[mf][nf][1];
            float d2 = sq0 - 2.f * acc[mf][nf][2];
            float d3 = sq1 - 2.f * acc[mf][nf][3];
            if (c0 != ra && (d0 < bva[mf] || (d0 == bva[mf] && c0 < bia[mf]))) { bva[mf] = d0; bia[mf] = c0; }
            if (c0 + 1 != ra && (d1 < bva[mf] || (d1 == bva[mf] && c0 + 1 < bia[mf]))) { bva[mf] = d1; bia[mf] = c0 + 1; }
            if (c0 != rb && (d2 < bvb[mf] || (d2 == bvb[mf] && c0 < bib[mf]))) { bvb[mf] = d2; bib[mf] = c0; }
            if (c0 + 1 != rb && (d3 < bvb[mf] || (d3 == bvb[mf] && c0 + 1 < bib[mf]))) { bvb[mf] = d3; bib[mf] = c0 + 1; }
        }
    }
    // reduce across the 4 lanes sharing each row (lane&3)
#pragma unroll
    for (int off = 1; off <= 2; off <<= 1) {
#pragma unroll
        for (int mf = 0; mf < 2; mf++) {
            float v = __shfl_xor_sync(0xffffffffu, bva[mf], off);
            int   i2 = __shfl_xor_sync(0xffffffffu, bia[mf], off);
            if (v < bva[mf] || (v == bva[mf] && i2 < bia[mf])) { bva[mf] = v; bia[mf] = i2; }
            v  = __shfl_xor_sync(0xffffffffu, bvb[mf], off);
            i2 = __shfl_xor_sync(0xffffffffu, bib[mf], off);
            if (v < bvb[mf] || (v == bvb[mf] && i2 < bib[mf])) { bvb[mf] = v; bib[mf] = i2; }
        }
    }
    if ((lane & 3) == 0) {
#pragma unroll
        for (int mf = 0; mf < 2; mf++) {
            int rt = warp_m * 32 + mf * 16 + (lane >> 2);
            redV[warp_n * 128 + rt] = bva[mf];  redI[warp_n * 128 + rt] = bia[mf];
            redV[warp_n * 128 + rt + 8] = bvb[mf]; redI[warp_n * 128 + rt + 8] = bib[mf];
        }
    }
    __syncthreads();
    if (tid < 128) {
        float v0 = redV[tid]; int i0 = redI[tid];
        float v1 = redV[128 + tid]; int i1 = redI[128 + tid];
        if (v1 < v0 || (v1 == v0 && i1 < i0)) { v0 = v1; i0 = i1; }
        g_pmin[band * NPTS + row0 + tid] = v0;
        g_pidx[band * NPTS + row0 + tid] = i0;
    }
}

// ---------------- kernel 3: reduce the 64 band partial argmins ----------------
__global__ void reduce_argmin_kernel() {
    int i = blockIdx.x * 256 + threadIdx.x;
    if (i >= NPTS) return;
    float bv = 1e30f;
    int bi = 0;
    for (int s = 0; s < NBAND; s++) {
        float v = g_pmin[s * NPTS + i];
        int id2 = g_pidx[s * NPTS + i];
        if (v < bv || (v == bv && id2 < bi)) { bv = v; bi = id2; }
    }
    g_closest[i] = bi;
}

// ---------------- kernel 4: fused Taylor-encoder + decoder (one warp per row) ----------------
#define MLP_SMEM_FLOATS (32768 + 2048 + 1024 + 1024 + 2048 + 8 * 320)

__global__ __launch_bounds__(256, 1) void mlp_kernel(
    const float* __restrict__ xs,
    const float* __restrict__ W1, const float* __restrict__ b1,
    const float* __restrict__ W2, const float* __restrict__ b2,
    const float* __restrict__ W3, const float* __restrict__ b3,
    const float* __restrict__ D1, const float* __restrict__ d1,
    const float* __restrict__ D2, const float* __restrict__ d2,
    const float* __restrict__ D3, const float* __restrict__ d3,
    float* __restrict__ out) {
    extern __shared__ float fsmem[];
    float* sD3t = fsmem;              // [64][512] transposed D3
    float* sW2t = sD3t + 32768;       // [64][32]
    float* sW3t = sW2t + 2048;        // [32][32]
    float* sD1t = sW3t + 1024;        // [32][32]
    float* sD2t = sD1t + 1024;        // [32][64]
    float* sScr = sD2t + 2048;        // 8 warps * 320

    const int tid = threadIdx.x;
    for (int i = tid; i < 512 * 64; i += 256) { int dd = i >> 6, k = i & 63; sD3t[k * 512 + dd] = D3[i]; }
    for (int i = tid; i < 32 * 64; i += 256)  { int o = i >> 6, k = i & 63; sW2t[k * 32 + o] = W2[i]; }
    for (int i = tid; i < 32 * 32; i += 256)  { int o = i >> 5, k = i & 31; sW3t[k * 32 + o] = W3[i]; sD1t[k * 32 + o] = D1[i]; }
    for (int i = tid; i < 64 * 32; i += 256)  { int o = i >> 5, k = i & 31; sD2t[k * 64 + o] = D2[i]; }
    __syncthreads();

    const int warp = tid >> 5, lane = tid & 31;
    const int row = blockIdx.x * 8 + warp;
    float* scr = sScr + warp * 320;
    float* su  = scr;
    float* sv  = scr + 64;
    float* sa2 = scr + 128;
    float* szs = scr + 160;
    float* sh1 = scr + 192;
    float* sh2 = scr + 224;

    const int j = g_closest[row];
    const float* xp  = xs + (size_t)row * DIM;
    const float* x0p = xs + (size_t)j * DIM;
    float xr[16], x0r[16];
#pragma unroll
    for (int t = 0; t < 16; t++) { xr[t] = xp[lane + 32 * t]; x0r[t] = x0p[lane + 32 * t]; }

    for (int o = 0; o < 64; o++) {
        const float* wp = W1 + o * DIM;
        float du = 0.f, dv = 0.f;
#pragma unroll
        for (int t = 0; t < 16; t++) {
            float w = __ldg(&wp[lane + 32 * t]);
            du += w * xr[t];
            dv += w * x0r[t];
        }
#pragma unroll
        for (int off = 16; off; off >>= 1) {
            du += __shfl_xor_sync(0xffffffffu, du, off);
            dv += __shfl_xor_sync(0xffffffffu, dv, off);
        }
        if (lane == 0) { float bb = __ldg(&b1[o]); su[o] = du + bb; sv[o] = dv + bb; }
    }
    __syncwarp();

#pragma unroll
    for (int h = 0; h < 2; h++) {
        int k = lane + 32 * h;
        float v = sv[k], u = su[k];
        su[k] = (v > 0.f) ? u : 0.f;
        sv[k] = (v > 0.f) ? v : 0.f;
    }
    __syncwarp();

    {
        int o = lane;
        float u2 = 0.f, v2 = 0.f;
#pragma unroll
        for (int k = 0; k < 64; k++) {
            float w = sW2t[k * 32 + o];
            u2 += w * su[k];
            v2 += w * sv[k];
        }
        float bb = __ldg(&b2[o]);
        u2 += bb; v2 += bb;
        sa2[o] = (v2 > 0.f) ? u2 : 0.f;
    }
    __syncwarp();
    {
        int o = lane;
        float z = __ldg(&b3[o]);
#pragma unroll
        for (int k = 0; k < 32; k++) z += sW3t[k * 32 + o] * sa2[k];
        szs[o] = z;
        out[(size_t)NPTS * DIM + (size_t)row * 32 + o] = z;
    }
    __syncwarp();

    {
        int o = lane;
        float h = __ldg(&d1[o]);
#pragma unroll
        for (int k = 0; k < 32; k++) h += sD1t[k * 32 + o] * szs[k];
        sh1[o] = fmaxf(h, 0.f);
    }
    __syncwarp();
#pragma unroll
    for (int hh = 0; hh < 2; hh++) {
        int o = lane + 32 * hh;
        float h = __ldg(&d2[o]);
#pragma unroll
        for (int k = 0; k < 32; k++) h += sD2t[k * 64 + o] * sh1[k];
        sh2[o] = fmaxf(h, 0.f);
    }
    __syncwarp();

#pragma unroll 4
    for (int t = 0; t < 16; t++) {
        int dcol = lane + 32 * t;
        float acc = __ldg(&d3[dcol]);
#pragma unroll
        for (int k = 0; k < 64; k++) acc += sD3t[k * 512 + dcol] * sh2[k];
        out[(size_t)row * DIM + dcol] = acc;
    }
}

// ---------------- launch ----------------
extern "C" void kernel_launch(void* const* d_in, const int* in_sizes, int n_in,
                              void* d_out, int out_size) {
    const float* xs = (const float*)d_in[0];
    const float* W1 = (const float*)d_in[1];
    const float* b1 = (const float*)d_in[2];
    const float* W2 = (const float*)d_in[3];
    const float* b2 = (const float*)d_in[4];
    const float* W3 = (const float*)d_in[5];
    const float* b3 = (const float*)d_in[6];
    const float* D1 = (const float*)d_in[7];
    const float* d1 = (const float*)d_in[8];
    const float* D2 = (const float*)d_in[9];
    const float* d2 = (const float*)d_in[10];
    const float* D3 = (const float*)d_in[11];
    const float* d3 = (const float*)d_in[12];
    float* out = (float*)d_out;

    convert_kernel<<<NPTS * DIM / 256, 256>>>(xs);
    row_norms_kernel<<<NPTS / 8, 256>>>(xs);

    cudaFuncSetAttribute(gram_argmin_hmma, cudaFuncAttributeMaxDynamicSharedMemorySize, SMEM_GEMM);
    dim3 g2(NPTS / TM, NPTS / TN);
    gram_argmin_hmma<<<g2, 256, SMEM_GEMM>>>();

    reduce_argmin_kernel<<<NPTS / 256, 256>>>();

    size_t smem_bytes = MLP_SMEM_FLOATS * sizeof(float);
    cudaFuncSetAttribute(mlp_kernel, cudaFuncAttributeMaxDynamicSharedMemorySize,
                         (int)smem_bytes);
    mlp_kernel<<<NPTS / 8, 256, smem_bytes>>>(xs, W1, b1, W2, b2, W3, b3,
                                              D1, d1, D2, d2, D3, d3, out);
}

// round 7
// speedup vs baseline: 2.1529x; 1.1670x over previous
#include <cuda_runtime.h>
#include <cuda_bf16.h>
#include <cstdint>

#define NPTS 8192
#define DIM  512
#define NBAND 32

// ---------------- device scratch (no allocations allowed) ----------------
__device__ float g_sq[NPTS];
__device__ float g_pmin[NBAND * NPTS];
__device__ int   g_pidx[NBAND * NPTS];
__device__ int   g_closest[NPTS];
__device__ __nv_bfloat16 g_xb[NPTS * 1024];  // per row: [hi(512) | lo(512)]

// ---------------- helpers ----------------
__device__ __forceinline__ uint32_t smem_u32(const void* p) {
    uint32_t a;
    asm("{ .reg .u64 t; cvta.to.shared.u64 t, %1; cvt.u32.u64 %0, t; }" : "=r"(a) : "l"(p));
    return a;
}
#define SWZ(b) ((b) ^ (((b) >> 3) & 0x70))

__device__ __forceinline__ void cp_async16(uint32_t dst, const void* src) {
    asm volatile("cp.async.cg.shared.global [%0], [%1], 16;" :: "r"(dst), "l"(src));
}

__device__ __forceinline__ void ldmatrix_x4(uint32_t* r, uint32_t addr) {
    asm volatile("ldmatrix.sync.aligned.m8n8.x4.shared.b16 {%0,%1,%2,%3}, [%4];"
                 : "=r"(r[0]), "=r"(r[1]), "=r"(r[2]), "=r"(r[3]) : "r"(addr));
}

__device__ __forceinline__ void mma16816(float* d, const uint32_t* a, uint32_t b0, uint32_t b1) {
    asm volatile(
        "mma.sync.aligned.m16n8k16.row.col.f32.bf16.bf16.f32 "
        "{%0,%1,%2,%3}, {%4,%5,%6,%7}, {%8,%9}, {%0,%1,%2,%3};"
        : "+f"(d[0]), "+f"(d[1]), "+f"(d[2]), "+f"(d[3])
        : "r"(a[0]), "r"(a[1]), "r"(a[2]), "r"(a[3]), "r"(b0), "r"(b1));
}

// ---------------- kernel 0: fp32 -> [hi|lo] bf16 split ----------------
__global__ void convert_kernel(const float* __restrict__ xs) {
    int i = blockIdx.x * 256 + threadIdx.x;  // over NPTS*DIM
    float x = xs[i];
    int row = i >> 9, col = i & 511;
    __nv_bfloat16 hi = __float2bfloat16(x);
    float lof = x - __bfloat162float(hi);
    g_xb[row * 1024 + col] = hi;
    g_xb[row * 1024 + 512 + col] = __float2bfloat16(lof);
}

// ---------------- kernel 1: row squared norms (fp32 exact) ----------------
__global__ void row_norms_kernel(const float* __restrict__ xs) {
    int warp = threadIdx.x >> 5, lane = threadIdx.x & 31;
    int row = blockIdx.x * 8 + warp;
    const float* p = xs + (size_t)row * DIM;
    float s = 0.f;
#pragma unroll
    for (int t = 0; t < 16; t++) {
        float v = p[lane + 32 * t];
        s += v * v;
    }
#pragma unroll
    for (int off = 16; off; off >>= 1) s += __shfl_xor_sync(0xffffffffu, s, off);
    if (lane == 0) g_sq[row] = s;
}

// ---------------- kernel 2: HMMA Gram + fused argmin ----------------
// CTA: 128x256 tile. 8 warps in 2x4 (warp_m x warp_n), warp tile 64x64.
// K = 1536 folded (hi.hi + hi.lo + lo.hi) as 24 chunks of 64 with source remap.
// 3-stage cp.async ring (one __syncthreads per chunk), SW128 software swizzle,
// ldmatrix + mma.sync, fused per-row argmin epilogue.
#define TM 128
#define TN 256
#define KB 64
#define NCHUNK 24
#define NS 3
#define A_BYTES (TM * 128)
#define B_BYTES (TN * 128)
#define STAGE_BYTES (A_BYTES + B_BYTES)
#define SM_SQ 0
#define SM_REDV 1024
#define SM_REDI 3072
#define SM_TILE0 5120
#define SMEM_GEMM (SM_TILE0 + NS * STAGE_BYTES)

__device__ __forceinline__ int a_koff(int c) {
    return (c < 16) ? (c & 7) * KB : 512 + (c - 16) * KB;
}
__device__ __forceinline__ int b_koff(int c) {
    return (c < 8) ? c * KB : (c < 16) ? 512 + (c - 8) * KB : (c - 16) * KB;
}

__global__ __launch_bounds__(256, 1) void gram_argmin_hmma() {
    extern __shared__ char smem[];
    const uint32_t sb = smem_u32(smem);
    float* sSq  = (float*)(smem + SM_SQ);
    float* redV = (float*)(smem + SM_REDV);
    int*   redI = (int*)(smem + SM_REDI);

    const int tid = threadIdx.x;
    const int lane = tid & 31, wid = tid >> 5;
    const int warp_m = wid & 1, warp_n = wid >> 1;   // 2 x 4
    const int row0 = blockIdx.x * TM;
    const int band = blockIdx.y;
    const int col0 = band * TN;

    sSq[tid] = g_sq[col0 + tid];

    float acc[4][8][4];
#pragma unroll
    for (int mf = 0; mf < 4; mf++)
#pragma unroll
        for (int nf = 0; nf < 8; nf++)
#pragma unroll
            for (int e = 0; e < 4; e++) acc[mf][nf][e] = 0.f;

    // ldmatrix lane addressing (16 rows x 16 halfwords)
    const int lm_r = lane & 15;
    const int lm_k = (lane >> 4) * 8;

    const __nv_bfloat16* gXr = g_xb + (size_t)row0 * 1024;
    const __nv_bfloat16* gXc = g_xb + (size_t)col0 * 1024;

    // staging: A 128 rows x 8 segs (1024 xfers, 4/thr), B 256 rows x 8 segs (2048, 8/thr)
#define STAGE_CHUNK(cc)                                                                  \
    do {                                                                                 \
        const int _st = (cc) % NS;                                                       \
        const uint32_t _sa = sb + SM_TILE0 + _st * STAGE_BYTES;                          \
        const uint32_t _sb2 = _sa + A_BYTES;                                             \
        const __nv_bfloat16* _gA = gXr + a_koff(cc);                                     \
        const __nv_bfloat16* _gB = gXc + b_koff(cc);                                     \
        _Pragma("unroll")                                                                \
        for (int _it = 0; _it < 4; _it++) {                                              \
            int _e = tid + _it * 256, _r = _e >> 3, _s = _e & 7;                         \
            cp_async16(_sa + SWZ(_r * 128 + _s * 16), _gA + (size_t)_r * 1024 + _s * 8); \
        }                                                                                \
        _Pragma("unroll")                                                                \
        for (int _it = 0; _it < 8; _it++) {                                              \
            int _e = tid + _it * 256, _r = _e >> 3, _s = _e & 7;                         \
            cp_async16(_sb2 + SWZ(_r * 128 + _s * 16), _gB + (size_t)_r * 1024 + _s * 8);\
        }                                                                                \
        asm volatile("cp.async.commit_group;");                                          \
    } while (0)

    STAGE_CHUNK(0);
    STAGE_CHUNK(1);

    for (int c = 0; c < NCHUNK; c++) {
        if (c + 1 < NCHUNK) asm volatile("cp.async.wait_group 1;");
        else                asm volatile("cp.async.wait_group 0;");
        __syncthreads();
        if (c + 2 < NCHUNK) STAGE_CHUNK(c + 2);

        const uint32_t Ab = sb + SM_TILE0 + (c % NS) * STAGE_BYTES;
        const uint32_t Bb = Ab + A_BYTES;
#pragma unroll
        for (int ks = 0; ks < 4; ks++) {
            const int k0 = ks * 16;
            uint32_t a[4][4];
#pragma unroll
            for (int mf = 0; mf < 4; mf++) {
                int r = warp_m * 64 + mf * 16 + lm_r;
                ldmatrix_x4(a[mf], Ab + SWZ(r * 128 + (k0 + lm_k) * 2));
            }
            uint32_t b[4][4];
#pragma unroll
            for (int p = 0; p < 4; p++) {
                int n = warp_n * 64 + p * 16 + lm_r;
                ldmatrix_x4(b[p], Bb + SWZ(n * 128 + (k0 + lm_k) * 2));
            }
#pragma unroll
            for (int mf = 0; mf < 4; mf++)
#pragma unroll
                for (int nf = 0; nf < 8; nf++)
                    mma16816(acc[mf][nf], a[mf], b[nf >> 1][nf & 1], b[nf >> 1][(nf & 1) + 2]);
        }
    }

    // ---------- fused argmin epilogue ----------
    // acc[mf][nf][e]: rows ra = warp_m*64+mf*16+(lane>>2), rb = ra+8
    //                 cols      = warp_n*64+nf*8+(lane&3)*2 + (e&1)
    float bva[4], bvb[4];
    int   bia[4], bib[4];
#pragma unroll
    for (int mf = 0; mf < 4; mf++) { bva[mf] = 1e30f; bvb[mf] = 1e30f; bia[mf] = 0; bib[mf] = 0; }

#pragma unroll
    for (int mf = 0; mf < 4; mf++) {
        const int ra = row0 + warp_m * 64 + mf * 16 + (lane >> 2);
        const int rb = ra + 8;
#pragma unroll
        for (int nf = 0; nf < 8; nf++) {
            const int lc = warp_n * 64 + nf * 8 + (lane & 3) * 2;
            const float sq0 = sSq[lc], sq1 = sSq[lc + 1];
            const int c0 = col0 + lc;
            float d0 = sq0 - 2.f * acc[mf][nf][0];
            float d1 = sq1 - 2.f * acc[mf][nf][1];
            float d2 = sq0 - 2.f * acc[mf][nf][2];
            float d3 = sq1 - 2.f * acc[mf][nf][3];
            if (c0 != ra && (d0 < bva[mf] || (d0 == bva[mf] && c0 < bia[mf]))) { bva[mf] = d0; bia[mf] = c0; }
            if (c0 + 1 != ra && (d1 < bva[mf] || (d1 == bva[mf] && c0 + 1 < bia[mf]))) { bva[mf] = d1; bia[mf] = c0 + 1; }
            if (c0 != rb && (d2 < bvb[mf] || (d2 == bvb[mf] && c0 < bib[mf]))) { bvb[mf] = d2; bib[mf] = c0; }
            if (c0 + 1 != rb && (d3 < bvb[mf] || (d3 == bvb[mf] && c0 + 1 < bib[mf]))) { bvb[mf] = d3; bib[mf] = c0 + 1; }
        }
    }
    // reduce across the 4 lanes sharing each row (lane&3)
#pragma unroll
    for (int off = 1; off <= 2; off <<= 1) {
#pragma unroll
        for (int mf = 0; mf < 4; mf++) {
            float v = __shfl_xor_sync(0xffffffffu, bva[mf], off);
            int   i2 = __shfl_xor_sync(0xffffffffu, bia[mf], off);
            if (v < bva[mf] || (v == bva[mf] && i2 < bia[mf])) { bva[mf] = v; bia[mf] = i2; }
            v  = __shfl_xor_sync(0xffffffffu, bvb[mf], off);
            i2 = __shfl_xor_sync(0xffffffffu, bib[mf], off);
            if (v < bvb[mf] || (v == bvb[mf] && i2 < bib[mf])) { bvb[mf] = v; bib[mf] = i2; }
        }
    }
    if ((lane & 3) == 0) {
#pragma unroll
        for (int mf = 0; mf < 4; mf++) {
            int rt = warp_m * 64 + mf * 16 + (lane >> 2);
            redV[warp_n * 128 + rt] = bva[mf];      redI[warp_n * 128 + rt] = bia[mf];
            redV[warp_n * 128 + rt + 8] = bvb[mf];  redI[warp_n * 128 + rt + 8] = bib[mf];
        }
    }
    __syncthreads();
    if (tid < 128) {
        float bv = redV[tid]; int bi = redI[tid];
#pragma unroll
        for (int wn = 1; wn < 4; wn++) {
            float v = redV[wn * 128 + tid]; int i2 = redI[wn * 128 + tid];
            if (v < bv || (v == bv && i2 < bi)) { bv = v; bi = i2; }
        }
        g_pmin[band * NPTS + row0 + tid] = bv;
        g_pidx[band * NPTS + row0 + tid] = bi;
    }
}

// ---------------- kernel 3: reduce the 32 band partial argmins ----------------
__global__ void reduce_argmin_kernel() {
    int i = blockIdx.x * 256 + threadIdx.x;
    if (i >= NPTS) return;
    float bv = 1e30f;
    int bi = 0;
    for (int s = 0; s < NBAND; s++) {
        float v = g_pmin[s * NPTS + i];
        int id2 = g_pidx[s * NPTS + i];
        if (v < bv || (v == bv && id2 < bi)) { bv = v; bi = id2; }
    }
    g_closest[i] = bi;
}

// ---------------- kernel 4: fused Taylor-encoder + decoder (one warp per row) ----------------
#define MLP_SMEM_FLOATS (32768 + 2048 + 1024 + 1024 + 2048 + 8 * 320)

__global__ __launch_bounds__(256, 1) void mlp_kernel(
    const float* __restrict__ xs,
    const float* __restrict__ W1, const float* __restrict__ b1,
    const float* __restrict__ W2, const float* __restrict__ b2,
    const float* __restrict__ W3, const float* __restrict__ b3,
    const float* __restrict__ D1, const float* __restrict__ d1,
    const float* __restrict__ D2, const float* __restrict__ d2,
    const float* __restrict__ D3, const float* __restrict__ d3,
    float* __restrict__ out) {
    extern __shared__ float fsmem[];
    float* sD3t = fsmem;              // [64][512] transposed D3
    float* sW2t = sD3t + 32768;       // [64][32]
    float* sW3t = sW2t + 2048;        // [32][32]
    float* sD1t = sW3t + 1024;        // [32][32]
    float* sD2t = sD1t + 1024;        // [32][64]
    float* sScr = sD2t + 2048;        // 8 warps * 320

    const int tid = threadIdx.x;
    for (int i = tid; i < 512 * 64; i += 256) { int dd = i >> 6, k = i & 63; sD3t[k * 512 + dd] = D3[i]; }
    for (int i = tid; i < 32 * 64; i += 256)  { int o = i >> 6, k = i & 63; sW2t[k * 32 + o] = W2[i]; }
    for (int i = tid; i < 32 * 32; i += 256)  { int o = i >> 5, k = i & 31; sW3t[k * 32 + o] = W3[i]; sD1t[k * 32 + o] = D1[i]; }
    for (int i = tid; i < 64 * 32; i += 256)  { int o = i >> 5, k = i & 31; sD2t[k * 64 + o] = D2[i]; }
    __syncthreads();

    const int warp = tid >> 5, lane = tid & 31;
    const int row = blockIdx.x * 8 + warp;
    float* scr = sScr + warp * 320;
    float* su  = scr;
    float* sv  = scr + 64;
    float* sa2 = scr + 128;
    float* szs = scr + 160;
    float* sh1 = scr + 192;
    float* sh2 = scr + 224;

    const int j = g_closest[row];
    const float* xp  = xs + (size_t)row * DIM;
    const float* x0p = xs + (size_t)j * DIM;
    float xr[16], x0r[16];
#pragma unroll
    for (int t = 0; t < 16; t++) { xr[t] = xp[lane + 32 * t]; x0r[t] = x0p[lane + 32 * t]; }

    for (int o = 0; o < 64; o++) {
        const float* wp = W1 + o * DIM;
        float du = 0.f, dv = 0.f;
#pragma unroll
        for (int t = 0; t < 16; t++) {
            float w = __ldg(&wp[lane + 32 * t]);
            du += w * xr[t];
            dv += w * x0r[t];
        }
#pragma unroll
        for (int off = 16; off; off >>= 1) {
            du += __shfl_xor_sync(0xffffffffu, du, off);
            dv += __shfl_xor_sync(0xffffffffu, dv, off);
        }
        if (lane == 0) { float bb = __ldg(&b1[o]); su[o] = du + bb; sv[o] = dv + bb; }
    }
    __syncwarp();

#pragma unroll
    for (int h = 0; h < 2; h++) {
        int k = lane + 32 * h;
        float v = sv[k], u = su[k];
        su[k] = (v > 0.f) ? u : 0.f;
        sv[k] = (v > 0.f) ? v : 0.f;
    }
    __syncwarp();

    {
        int o = lane;
        float u2 = 0.f, v2 = 0.f;
#pragma unroll
        for (int k = 0; k < 64; k++) {
            float w = sW2t[k * 32 + o];
            u2 += w * su[k];
            v2 += w * sv[k];
        }
        float bb = __ldg(&b2[o]);
        u2 += bb; v2 += bb;
        sa2[o] = (v2 > 0.f) ? u2 : 0.f;
    }
    __syncwarp();
    {
        int o = lane;
        float z = __ldg(&b3[o]);
#pragma unroll
        for (int k = 0; k < 32; k++) z += sW3t[k * 32 + o] * sa2[k];
        szs[o] = z;
        out[(size_t)NPTS * DIM + (size_t)row * 32 + o] = z;
    }
    __syncwarp();

    {
        int o = lane;
        float h = __ldg(&d1[o]);
#pragma unroll
        for (int k = 0; k < 32; k++) h += sD1t[k * 32 + o] * szs[k];
        sh1[o] = fmaxf(h, 0.f);
    }
    __syncwarp();
#pragma unroll
    for (int hh = 0; hh < 2; hh++) {
        int o = lane + 32 * hh;
        float h = __ldg(&d2[o]);
#pragma unroll
        for (int k = 0; k < 32; k++) h += sD2t[k * 64 + o] * sh1[k];
        sh2[o] = fmaxf(h, 0.f);
    }
    __syncwarp();

#pragma unroll 4
    for (int t = 0; t < 16; t++) {
        int dcol = lane + 32 * t;
        float acc = __ldg(&d3[dcol]);
#pragma unroll
        for (int k = 0; k < 64; k++) acc += sD3t[k * 512 + dcol] * sh2[k];
        out[(size_t)row * DIM + dcol] = acc;
    }
}

// ---------------- launch ----------------
extern "C" void kernel_launch(void* const* d_in, const int* in_sizes, int n_in,
                              void* d_out, int out_size) {
    const float* xs = (const float*)d_in[0];
    const float* W1 = (const float*)d_in[1];
    const float* b1 = (const float*)d_in[2];
    const float* W2 = (const float*)d_in[3];
    const float* b2 = (const float*)d_in[4];
    const float* W3 = (const float*)d_in[5];
    const float* b3 = (const float*)d_in[6];
    const float* D1 = (const float*)d_in[7];
    const float* d1 = (const float*)d_in[8];
    const float* D2 = (const float*)d_in[9];
    const float* d2 = (const float*)d_in[10];
    const float* D3 = (const float*)d_in[11];
    const float* d3 = (const float*)d_in[12];
    float* out = (float*)d_out;

    convert_kernel<<<NPTS * DIM / 256, 256>>>(xs);
    row_norms_kernel<<<NPTS / 8, 256>>>(xs);

    cudaFuncSetAttribute(gram_argmin_hmma, cudaFuncAttributeMaxDynamicSharedMemorySize, SMEM_GEMM);
    dim3 g2(NPTS / TM, NPTS / TN);
    gram_argmin_hmma<<<g2, 256, SMEM_GEMM>>>();

    reduce_argmin_kernel<<<NPTS / 256, 256>>>();

    size_t smem_bytes = MLP_SMEM_FLOATS * sizeof(float);
    cudaFuncSetAttribute(mlp_kernel, cudaFuncAttributeMaxDynamicSharedMemorySize,
                         (int)smem_bytes);
    mlp_kernel<<<NPTS / 8, 256, smem_bytes>>>(xs, W1, b1, W2, b2, W3, b3,
                                              D1, d1, D2, d2, D3, d3, out);
}

// round 8
// speedup vs baseline: 3.1360x; 1.4567x over previous
#include <cuda_runtime.h>
#include <cuda_bf16.h>
#include <cstdint>
#include <cmath>

#define NPTS 8192
#define DIM  512
#define NBAND 64
#define NBLK 64

// ---------------- device scratch (no allocations allowed) ----------------
__device__ float g_sq[NPTS];
__device__ float g_pmin[NBAND * NPTS];
__device__ int   g_pidx[NBAND * NPTS];
__device__ int   g_closest[NPTS];
__device__ __nv_bfloat16 g_xb[NPTS * 1024];  // per row: [hi(512) | lo(512)]

// ---------------- helpers ----------------
__device__ __forceinline__ uint32_t smem_u32(const void* p) {
    uint32_t a;
    asm("{ .reg .u64 t; cvta.to.shared.u64 t, %1; cvt.u32.u64 %0, t; }" : "=r"(a) : "l"(p));
    return a;
}
#define SWZ(b) ((b) ^ (((b) >> 3) & 0x70))

__device__ __forceinline__ void cp_async16(uint32_t dst, const void* src) {
    asm volatile("cp.async.cg.shared.global [%0], [%1], 16;" :: "r"(dst), "l"(src));
}

__device__ __forceinline__ void ldmatrix_x4(uint32_t* r, uint32_t addr) {
    asm volatile("ldmatrix.sync.aligned.m8n8.x4.shared.b16 {%0,%1,%2,%3}, [%4];"
                 : "=r"(r[0]), "=r"(r[1]), "=r"(r[2]), "=r"(r[3]) : "r"(addr));
}

__device__ __forceinline__ void mma16816(float* d, const uint32_t* a, uint32_t b0, uint32_t b1) {
    asm volatile(
        "mma.sync.aligned.m16n8k16.row.col.f32.bf16.bf16.f32 "
        "{%0,%1,%2,%3}, {%4,%5,%6,%7}, {%8,%9}, {%0,%1,%2,%3};"
        : "+f"(d[0]), "+f"(d[1]), "+f"(d[2]), "+f"(d[3])
        : "r"(a[0]), "r"(a[1]), "r"(a[2]), "r"(a[3]), "r"(b0), "r"(b1));
}

// ---------------- kernel 0: fp32 -> [hi|lo] bf16 split ----------------
__global__ void convert_kernel(const float* __restrict__ xs) {
    int i = blockIdx.x * 256 + threadIdx.x;  // over NPTS*DIM
    float x = xs[i];
    int row = i >> 9, col = i & 511;
    __nv_bfloat16 hi = __float2bfloat16(x);
    float lof = x - __bfloat162float(hi);
    g_xb[row * 1024 + col] = hi;
    g_xb[row * 1024 + 512 + col] = __float2bfloat16(lof);
}

// ---------------- kernel 1: row squared norms (fp32 exact) ----------------
__global__ void row_norms_kernel(const float* __restrict__ xs) {
    int warp = threadIdx.x >> 5, lane = threadIdx.x & 31;
    int row = blockIdx.x * 8 + warp;
    const float* p = xs + (size_t)row * DIM;
    float s = 0.f;
#pragma unroll
    for (int t = 0; t < 16; t++) {
        float v = p[lane + 32 * t];
        s += v * v;
    }
#pragma unroll
    for (int off = 16; off; off >>= 1) s += __shfl_xor_sync(0xffffffffu, s, off);
    if (lane == 0) g_sq[row] = s;
}

// ---------------- kernel 2: triangular HMMA Gram + double-sided argmin ----------------
// Grid: 2080 CTAs over block pairs (I<=J) of 64 row/col blocks (128 each).
// CTA tile 128x128, 8 warps 4x2 (warp tile 32x64). K=1536 folded hi/lo, 24
// chunks of 64, 3-stage cp.async ring. Epilogue harvests the tile twice:
// rows of I vs cols of J (band J) and transposed cols vs rows (band I).
#define TM 128
#define TN 128
#define KB 64
#define NCHUNK 24
#define NS 3
#define A_BYTES (TM * 128)
#define B_BYTES (TN * 128)
#define STAGE_BYTES (A_BYTES + B_BYTES)
#define SM_SQC 0
#define SM_SQR 512
#define SM_REDV 1024
#define SM_REDI 2048
#define SM_COLV 3072
#define SM_COLI 5120
#define SM_TILE0 7168
#define SMEM_GEMM (SM_TILE0 + NS * STAGE_BYTES)

__device__ __forceinline__ int a_koff(int c) {
    return (c < 16) ? (c & 7) * KB : 512 + (c - 16) * KB;
}
__device__ __forceinline__ int b_koff(int c) {
    return (c < 8) ? c * KB : (c < 16) ? 512 + (c - 8) * KB : (c - 16) * KB;
}
__device__ __forceinline__ int tri_cum(int I) { return 64 * I - (I * (I - 1)) / 2; }

__global__ __launch_bounds__(256, 2) void gram_argmin_tri() {
    extern __shared__ char smem[];
    const uint32_t sb = smem_u32(smem);
    float* sSqC = (float*)(smem + SM_SQC);
    float* sSqR = (float*)(smem + SM_SQR);
    float* redV = (float*)(smem + SM_REDV);
    int*   redI = (int*)(smem + SM_REDI);
    float* colV = (float*)(smem + SM_COLV);
    int*   colI = (int*)(smem + SM_COLI);

    const int tid = threadIdx.x;
    const int lane = tid & 31, wid = tid >> 5;
    const int warp_m = wid & 3, warp_n = wid >> 2;   // 4 x 2

    // block pair (I <= J) from linear index
    const int t = blockIdx.x;
    int I = (int)((129.0 - sqrt(129.0 * 129.0 - 8.0 * (double)t)) * 0.5);
    while (tri_cum(I + 1) <= t) I++;
    while (tri_cum(I) > t) I--;
    const int J = I + (t - tri_cum(I));
    const int row0 = I * TM;
    const int col0 = J * TN;
    const bool diag = (I == J);

    if (tid < 128) {
        sSqC[tid] = g_sq[col0 + tid];
        sSqR[tid] = g_sq[row0 + tid];
    }

    float acc[2][8][4];
#pragma unroll
    for (int mf = 0; mf < 2; mf++)
#pragma unroll
        for (int nf = 0; nf < 8; nf++)
#pragma unroll
            for (int e = 0; e < 4; e++) acc[mf][nf][e] = 0.f;

    const int lm_r = lane & 15;
    const int lm_k = (lane >> 4) * 8;

    const __nv_bfloat16* gXr = g_xb + (size_t)row0 * 1024;
    const __nv_bfloat16* gXc = g_xb + (size_t)col0 * 1024;

    // staging: A/B each 128 rows x 8 segs of 16B -> 4 cp.async per tensor per thread
#define STAGE_CHUNK(cc)                                                                  \
    do {                                                                                 \
        const int _st = (cc) % NS;                                                       \
        const uint32_t _sa = sb + SM_TILE0 + _st * STAGE_BYTES;                          \
        const uint32_t _sb2 = _sa + A_BYTES;                                             \
        const __nv_bfloat16* _gA = gXr + a_koff(cc);                                     \
        const __nv_bfloat16* _gB = gXc + b_koff(cc);                                     \
        _Pragma("unroll")                                                                \
        for (int _it = 0; _it < 4; _it++) {                                              \
            int _e = tid + _it * 256, _r = _e >> 3, _s = _e & 7;                         \
            cp_async16(_sa + SWZ(_r * 128 + _s * 16), _gA + (size_t)_r * 1024 + _s * 8); \
            cp_async16(_sb2 + SWZ(_r * 128 + _s * 16), _gB + (size_t)_r * 1024 + _s * 8);\
        }                                                                                \
        asm volatile("cp.async.commit_group;");                                          \
    } while (0)

    STAGE_CHUNK(0);
    STAGE_CHUNK(1);

    for (int c = 0; c < NCHUNK; c++) {
        if (c + 1 < NCHUNK) asm volatile("cp.async.wait_group 1;");
        else                asm volatile("cp.async.wait_group 0;");
        __syncthreads();
        if (c + 2 < NCHUNK) STAGE_CHUNK(c + 2);

        const uint32_t Ab = sb + SM_TILE0 + (c % NS) * STAGE_BYTES;
        const uint32_t Bb = Ab + A_BYTES;
#pragma unroll
        for (int ks = 0; ks < 4; ks++) {
            const int k0 = ks * 16;
            uint32_t a[2][4];
#pragma unroll
            for (int mf = 0; mf < 2; mf++) {
                int r = warp_m * 32 + mf * 16 + lm_r;
                ldmatrix_x4(a[mf], Ab + SWZ(r * 128 + (k0 + lm_k) * 2));
            }
            uint32_t b[4][4];
#pragma unroll
            for (int p = 0; p < 4; p++) {
                int n = warp_n * 64 + p * 16 + lm_r;
                ldmatrix_x4(b[p], Bb + SWZ(n * 128 + (k0 + lm_k) * 2));
            }
#pragma unroll
            for (int mf = 0; mf < 2; mf++)
#pragma unroll
                for (int nf = 0; nf < 8; nf++)
                    mma16816(acc[mf][nf], a[mf], b[nf >> 1][nf & 1], b[nf >> 1][(nf & 1) + 2]);
        }
    }

    // ---------- row-side argmin: rows of block I over cols of block J (band J) ----------
    // acc[mf][nf][e]: rows ra = warp_m*32+mf*16+(lane>>2), rb = ra+8
    //                 cols      = warp_n*64+nf*8+(lane&3)*2 + (e&1)
    {
        float bva[2], bvb[2];
        int   bia[2], bib[2];
#pragma unroll
        for (int mf = 0; mf < 2; mf++) { bva[mf] = 1e30f; bvb[mf] = 1e30f; bia[mf] = 0; bib[mf] = 0; }

#pragma unroll
        for (int mf = 0; mf < 2; mf++) {
            const int ra = row0 + warp_m * 32 + mf * 16 + (lane >> 2);
            const int rb = ra + 8;
#pragma unroll
            for (int nf = 0; nf < 8; nf++) {
                const int lc = warp_n * 64 + nf * 8 + (lane & 3) * 2;
                const float sq0 = sSqC[lc], sq1 = sSqC[lc + 1];
                const int c0 = col0 + lc;
                float d0 = sq0 - 2.f * acc[mf][nf][0];
                float d1 = sq1 - 2.f * acc[mf][nf][1];
                float d2 = sq0 - 2.f * acc[mf][nf][2];
                float d3 = sq1 - 2.f * acc[mf][nf][3];
                if (c0 != ra && (d0 < bva[mf] || (d0 == bva[mf] && c0 < bia[mf]))) { bva[mf] = d0; bia[mf] = c0; }
                if (c0 + 1 != ra && (d1 < bva[mf] || (d1 == bva[mf] && c0 + 1 < bia[mf]))) { bva[mf] = d1; bia[mf] = c0 + 1; }
                if (c0 != rb && (d2 < bvb[mf] || (d2 == bvb[mf] && c0 < bib[mf]))) { bvb[mf] = d2; bib[mf] = c0; }
                if (c0 + 1 != rb && (d3 < bvb[mf] || (d3 == bvb[mf] && c0 + 1 < bib[mf]))) { bvb[mf] = d3; bib[mf] = c0 + 1; }
            }
        }
#pragma unroll
        for (int off = 1; off <= 2; off <<= 1) {
#pragma unroll
            for (int mf = 0; mf < 2; mf++) {
                float v = __shfl_xor_sync(0xffffffffu, bva[mf], off);
                int   i2 = __shfl_xor_sync(0xffffffffu, bia[mf], off);
                if (v < bva[mf] || (v == bva[mf] && i2 < bia[mf])) { bva[mf] = v; bia[mf] = i2; }
                v  = __shfl_xor_sync(0xffffffffu, bvb[mf], off);
                i2 = __shfl_xor_sync(0xffffffffu, bib[mf], off);
                if (v < bvb[mf] || (v == bvb[mf] && i2 < bib[mf])) { bvb[mf] = v; bib[mf] = i2; }
            }
        }
        if ((lane & 3) == 0) {
#pragma unroll
            for (int mf = 0; mf < 2; mf++) {
                int rt = warp_m * 32 + mf * 16 + (lane >> 2);
                redV[warp_n * 128 + rt] = bva[mf];      redI[warp_n * 128 + rt] = bia[mf];
                redV[warp_n * 128 + rt + 8] = bvb[mf];  redI[warp_n * 128 + rt + 8] = bib[mf];
            }
        }
    }

    // ---------- col-side argmin: cols of block J over rows of block I (band I) ----------
    if (!diag) {
#pragma unroll
        for (int nf = 0; nf < 8; nf++) {
#pragma unroll
            for (int e = 0; e < 2; e++) {
                float bv = 1e30f;
                int bi = 0;
#pragma unroll
                for (int mf = 0; mf < 2; mf++) {
                    int rla = warp_m * 32 + mf * 16 + (lane >> 2);
                    float da = sSqR[rla] - 2.f * acc[mf][nf][e];
                    float db = sSqR[rla + 8] - 2.f * acc[mf][nf][e + 2];
                    int ga = row0 + rla, gb = ga + 8;
                    if (da < bv || (da == bv && ga < bi)) { bv = da; bi = ga; }
                    if (db < bv || (db == bv && gb < bi)) { bv = db; bi = gb; }
                }
#pragma unroll
                for (int off = 4; off <= 16; off <<= 1) {
                    float v = __shfl_xor_sync(0xffffffffu, bv, off);
                    int i2  = __shfl_xor_sync(0xffffffffu, bi, off);
                    if (v < bv || (v == bv && i2 < bi)) { bv = v; bi = i2; }
                }
                if (lane < 4) {
                    int cl = warp_n * 64 + nf * 8 + lane * 2 + e;
                    colV[warp_m * 128 + cl] = bv;
                    colI[warp_m * 128 + cl] = bi;
                }
            }
        }
    }
    __syncthreads();

    if (tid < 128) {
        // band J <- rows of block I
        float bv = redV[tid]; int bi = redI[tid];
        float v = redV[128 + tid]; int i2 = redI[128 + tid];
        if (v < bv || (v == bv && i2 < bi)) { bv = v; bi = i2; }
        g_pmin[J * NPTS + row0 + tid] = bv;
        g_pidx[J * NPTS + row0 + tid] = bi;
        if (!diag) {
            // band I <- cols of block J
            bv = colV[tid]; bi = colI[tid];
#pragma unroll
            for (int wm = 1; wm < 4; wm++) {
                v = colV[wm * 128 + tid]; i2 = colI[wm * 128 + tid];
                if (v < bv || (v == bv && i2 < bi)) { bv = v; bi = i2; }
            }
            g_pmin[I * NPTS + col0 + tid] = bv;
            g_pidx[I * NPTS + col0 + tid] = bi;
        }
    }
}

// ---------------- kernel 3: reduce the 64 band partial argmins ----------------
__global__ void reduce_argmin_kernel() {
    int i = blockIdx.x * 256 + threadIdx.x;
    if (i >= NPTS) return;
    float bv = 1e30f;
    int bi = 0;
    for (int s = 0; s < NBAND; s++) {
        float v = g_pmin[s * NPTS + i];
        int id2 = g_pidx[s * NPTS + i];
        if (v < bv || (v == bv && id2 < bi)) { bv = v; bi = id2; }
    }
    g_closest[i] = bi;
}

// ---------------- kernel 4: fused Taylor-encoder + decoder (one warp per row) ----------------
#define MLP_SMEM_FLOATS (32768 + 2048 + 1024 + 1024 + 2048 + 8 * 320)

__global__ __launch_bounds__(256, 1) void mlp_kernel(
    const float* __restrict__ xs,
    const float* __restrict__ W1, const float* __restrict__ b1,
    const float* __restrict__ W2, const float* __restrict__ b2,
    const float* __restrict__ W3, const float* __restrict__ b3,
    const float* __restrict__ D1, const float* __restrict__ d1,
    const float* __restrict__ D2, const float* __restrict__ d2,
    const float* __restrict__ D3, const float* __restrict__ d3,
    float* __restrict__ out) {
    extern __shared__ float fsmem[];
    float* sD3t = fsmem;              // [64][512] transposed D3
    float* sW2t = sD3t + 32768;       // [64][32]
    float* sW3t = sW2t + 2048;        // [32][32]
    float* sD1t = sW3t + 1024;        // [32][32]
    float* sD2t = sD1t + 1024;        // [32][64]
    float* sScr = sD2t + 2048;        // 8 warps * 320

    const int tid = threadIdx.x;
    for (int i = tid; i < 512 * 64; i += 256) { int dd = i >> 6, k = i & 63; sD3t[k * 512 + dd] = D3[i]; }
    for (int i = tid; i < 32 * 64; i += 256)  { int o = i >> 6, k = i & 63; sW2t[k * 32 + o] = W2[i]; }
    for (int i = tid; i < 32 * 32; i += 256)  { int o = i >> 5, k = i & 31; sW3t[k * 32 + o] = W3[i]; sD1t[k * 32 + o] = D1[i]; }
    for (int i = tid; i < 64 * 32; i += 256)  { int o = i >> 5, k = i & 31; sD2t[k * 64 + o] = D2[i]; }
    __syncthreads();

    const int warp = tid >> 5, lane = tid & 31;
    const int row = blockIdx.x * 8 + warp;
    float* scr = sScr + warp * 320;
    float* su  = scr;
    float* sv  = scr + 64;
    float* sa2 = scr + 128;
    float* szs = scr + 160;
    float* sh1 = scr + 192;
    float* sh2 = scr + 224;

    const int j = g_closest[row];
    const float* xp  = xs + (size_t)row * DIM;
    const float* x0p = xs + (size_t)j * DIM;
    float xr[16], x0r[16];
#pragma unroll
    for (int t = 0; t < 16; t++) { xr[t] = xp[lane + 32 * t]; x0r[t] = x0p[lane + 32 * t]; }

    for (int o = 0; o < 64; o++) {
        const float* wp = W1 + o * DIM;
        float du = 0.f, dv = 0.f;
#pragma unroll
        for (int t = 0; t < 16; t++) {
            float w = __ldg(&wp[lane + 32 * t]);
            du += w * xr[t];
            dv += w * x0r[t];
        }
#pragma unroll
        for (int off = 16; off; off >>= 1) {
            du += __shfl_xor_sync(0xffffffffu, du, off);
            dv += __shfl_xor_sync(0xffffffffu, dv, off);
        }
        if (lane == 0) { float bb = __ldg(&b1[o]); su[o] = du + bb; sv[o] = dv + bb; }
    }
    __syncwarp();

#pragma unroll
    for (int h = 0; h < 2; h++) {
        int k = lane + 32 * h;
        float v = sv[k], u = su[k];
        su[k] = (v > 0.f) ? u : 0.f;
        sv[k] = (v > 0.f) ? v : 0.f;
    }
    __syncwarp();

    {
        int o = lane;
        float u2 = 0.f, v2 = 0.f;
#pragma unroll
        for (int k = 0; k < 64; k++) {
            float w = sW2t[k * 32 + o];
            u2 += w * su[k];
            v2 += w * sv[k];
        }
        float bb = __ldg(&b2[o]);
        u2 += bb; v2 += bb;
        sa2[o] = (v2 > 0.f) ? u2 : 0.f;
    }
    __syncwarp();
    {
        int o = lane;
        float z = __ldg(&b3[o]);
#pragma unroll
        for (int k = 0; k < 32; k++) z += sW3t[k * 32 + o] * sa2[k];
        szs[o] = z;
        out[(size_t)NPTS * DIM + (size_t)row * 32 + o] = z;
    }
    __syncwarp();

    {
        int o = lane;
        float h = __ldg(&d1[o]);
#pragma unroll
        for (int k = 0; k < 32; k++) h += sD1t[k * 32 + o] * szs[k];
        sh1[o] = fmaxf(h, 0.f);
    }
    __syncwarp();
#pragma unroll
    for (int hh = 0; hh < 2; hh++) {
        int o = lane + 32 * hh;
        float h = __ldg(&d2[o]);
#pragma unroll
        for (int k = 0; k < 32; k++) h += sD2t[k * 64 + o] * sh1[k];
        sh2[o] = fmaxf(h, 0.f);
    }
    __syncwarp();

#pragma unroll 4
    for (int t = 0; t < 16; t++) {
        int dcol = lane + 32 * t;
        float acc = __ldg(&d3[dcol]);
#pragma unroll
        for (int k = 0; k < 64; k++) acc += sD3t[k * 512 + dcol] * sh2[k];
        out[(size_t)row * DIM + dcol] = acc;
    }
}

// ---------------- launch ----------------
extern "C" void kernel_launch(void* const* d_in, const int* in_sizes, int n_in,
                              void* d_out, int out_size) {
    const float* xs = (const float*)d_in[0];
    const float* W1 = (const float*)d_in[1];
    const float* b1 = (const float*)d_in[2];
    const float* W2 = (const float*)d_in[3];
    const float* b2 = (const float*)d_in[4];
    const float* W3 = (const float*)d_in[5];
    const float* b3 = (const float*)d_in[6];
    const float* D1 = (const float*)d_in[7];
    const float* d1 = (const float*)d_in[8];
    const float* D2 = (const float*)d_in[9];
    const float* d2 = (const float*)d_in[10];
    const float* D3 = (const float*)d_in[11];
    const float* d3 = (const float*)d_in[12];
    float* out = (float*)d_out;

    convert_kernel<<<NPTS * DIM / 256, 256>>>(xs);
    row_norms_kernel<<<NPTS / 8, 256>>>(xs);

    cudaFuncSetAttribute(gram_argmin_tri, cudaFuncAttributeMaxDynamicSharedMemorySize, SMEM_GEMM);
    const int npairs = NBLK * (NBLK + 1) / 2;  // 2080
    gram_argmin_tri<<<npairs, 256, SMEM_GEMM>>>();

    reduce_argmin_kernel<<<NPTS / 256, 256>>>();

    size_t smem_bytes = MLP_SMEM_FLOATS * sizeof(float);
    cudaFuncSetAttribute(mlp_kernel, cudaFuncAttributeMaxDynamicSharedMemorySize,
                         (int)smem_bytes);
    mlp_kernel<<<NPTS / 8, 256, smem_bytes>>>(xs, W1, b1, W2, b2, W3, b3,
                                              D1, d1, D2, d2, D3, d3, out);
}

// round 9
// speedup vs baseline: 5.0400x; 1.6072x over previous
#include <cuda_runtime.h>
#include <cuda_bf16.h>
#include <cstdint>
#include <cmath>

#define NPTS 8192
#define DIM  512
#define NBAND 64
#define NBLK 64

// ---------------- device scratch (no allocations allowed) ----------------
__device__ float g_sq[NPTS];
__device__ float g_pmin[NBAND * NPTS];
__device__ int   g_pidx[NBAND * NPTS];
__device__ int   g_closest[NPTS];
__device__ __nv_bfloat16 g_xb[NPTS * 1024];  // per row: [hi(512) | lo(512)]
__device__ float g_Z1[NPTS * 64];            // encoder layer-1 pre-activation
__device__ float g_Z2[NPTS * 32];            // encoder layer-2 pre-activation (x0 path)
__device__ float g_h2[NPTS * 64];            // decoder hidden-2 activations

// ---------------- helpers ----------------
__device__ __forceinline__ uint32_t smem_u32(const void* p) {
    uint32_t a;
    asm("{ .reg .u64 t; cvta.to.shared.u64 t, %1; cvt.u32.u64 %0, t; }" : "=r"(a) : "l"(p));
    return a;
}
#define SWZ(b) ((b) ^ (((b) >> 3) & 0x70))

__device__ __forceinline__ void cp_async16(uint32_t dst, const void* src) {
    asm volatile("cp.async.cg.shared.global [%0], [%1], 16;" :: "r"(dst), "l"(src));
}

__device__ __forceinline__ void ldmatrix_x4(uint32_t* r, uint32_t addr) {
    asm volatile("ldmatrix.sync.aligned.m8n8.x4.shared.b16 {%0,%1,%2,%3}, [%4];"
                 : "=r"(r[0]), "=r"(r[1]), "=r"(r[2]), "=r"(r[3]) : "r"(addr));
}

__device__ __forceinline__ void mma16816(float* d, const uint32_t* a, uint32_t b0, uint32_t b1) {
    asm volatile(
        "mma.sync.aligned.m16n8k16.row.col.f32.bf16.bf16.f32 "
        "{%0,%1,%2,%3}, {%4,%5,%6,%7}, {%8,%9}, {%0,%1,%2,%3};"
        : "+f"(d[0]), "+f"(d[1]), "+f"(d[2]), "+f"(d[3])
        : "r"(a[0]), "r"(a[1]), "r"(a[2]), "r"(a[3]), "r"(b0), "r"(b1));
}

// ---------------- kernel 0: fp32 -> [hi|lo] bf16 split ----------------
__global__ void convert_kernel(const float* __restrict__ xs) {
    int i = blockIdx.x * 256 + threadIdx.x;  // over NPTS*DIM
    float x = xs[i];
    int row = i >> 9, col = i & 511;
    __nv_bfloat16 hi = __float2bfloat16(x);
    float lof = x - __bfloat162float(hi);
    g_xb[row * 1024 + col] = hi;
    g_xb[row * 1024 + 512 + col] = __float2bfloat16(lof);
}

// ---------------- kernel 1: row squared norms (fp32 exact) ----------------
__global__ void row_norms_kernel(const float* __restrict__ xs) {
    int warp = threadIdx.x >> 5, lane = threadIdx.x & 31;
    int row = blockIdx.x * 8 + warp;
    const float* p = xs + (size_t)row * DIM;
    float s = 0.f;
#pragma unroll
    for (int t = 0; t < 16; t++) {
        float v = p[lane + 32 * t];
        s += v * v;
    }
#pragma unroll
    for (int off = 16; off; off >>= 1) s += __shfl_xor_sync(0xffffffffu, s, off);
    if (lane == 0) g_sq[row] = s;
}

// ---------------- kernel 2: triangular HMMA Gram + double-sided argmin ----------------
#define TM 128
#define TN 128
#define KB 64
#define NCHUNK 24
#define NS 3
#define A_BYTES (TM * 128)
#define B_BYTES (TN * 128)
#define STAGE_BYTES (A_BYTES + B_BYTES)
#define SM_SQC 0
#define SM_SQR 512
#define SM_REDV 1024
#define SM_REDI 2048
#define SM_COLV 3072
#define SM_COLI 5120
#define SM_TILE0 7168
#define SMEM_GEMM (SM_TILE0 + NS * STAGE_BYTES)

__device__ __forceinline__ int a_koff(int c) {
    return (c < 16) ? (c & 7) * KB : 512 + (c - 16) * KB;
}
__device__ __forceinline__ int b_koff(int c) {
    return (c < 8) ? c * KB : (c < 16) ? 512 + (c - 8) * KB : (c - 16) * KB;
}
__device__ __forceinline__ int tri_cum(int I) { return 64 * I - (I * (I - 1)) / 2; }

__global__ __launch_bounds__(256, 2) void gram_argmin_tri() {
    extern __shared__ char smem[];
    const uint32_t sb = smem_u32(smem);
    float* sSqC = (float*)(smem + SM_SQC);
    float* sSqR = (float*)(smem + SM_SQR);
    float* redV = (float*)(smem + SM_REDV);
    int*   redI = (int*)(smem + SM_REDI);
    float* colV = (float*)(smem + SM_COLV);
    int*   colI = (int*)(smem + SM_COLI);

    const int tid = threadIdx.x;
    const int lane = tid & 31, wid = tid >> 5;
    const int warp_m = wid & 3, warp_n = wid >> 2;   // 4 x 2

    const int t = blockIdx.x;
    int I = (int)((129.0 - sqrt(129.0 * 129.0 - 8.0 * (double)t)) * 0.5);
    while (tri_cum(I + 1) <= t) I++;
    while (tri_cum(I) > t) I--;
    const int J = I + (t - tri_cum(I));
    const int row0 = I * TM;
    const int col0 = J * TN;
    const bool diag = (I == J);

    if (tid < 128) {
        sSqC[tid] = g_sq[col0 + tid];
        sSqR[tid] = g_sq[row0 + tid];
    }

    float acc[2][8][4];
#pragma unroll
    for (int mf = 0; mf < 2; mf++)
#pragma unroll
        for (int nf = 0; nf < 8; nf++)
#pragma unroll
            for (int e = 0; e < 4; e++) acc[mf][nf][e] = 0.f;

    const int lm_r = lane & 15;
    const int lm_k = (lane >> 4) * 8;

    const __nv_bfloat16* gXr = g_xb + (size_t)row0 * 1024;
    const __nv_bfloat16* gXc = g_xb + (size_t)col0 * 1024;

#define STAGE_CHUNK(cc)                                                                  \
    do {                                                                                 \
        const int _st = (cc) % NS;                                                       \
        const uint32_t _sa = sb + SM_TILE0 + _st * STAGE_BYTES;                          \
        const uint32_t _sb2 = _sa + A_BYTES;                                             \
        const __nv_bfloat16* _gA = gXr + a_koff(cc);                                     \
        const __nv_bfloat16* _gB = gXc + b_koff(cc);                                     \
        _Pragma("unroll")                                                                \
        for (int _it = 0; _it < 4; _it++) {                                              \
            int _e = tid + _it * 256, _r = _e >> 3, _s = _e & 7;                         \
            cp_async16(_sa + SWZ(_r * 128 + _s * 16), _gA + (size_t)_r * 1024 + _s * 8); \
            cp_async16(_sb2 + SWZ(_r * 128 + _s * 16), _gB + (size_t)_r * 1024 + _s * 8);\
        }                                                                                \
        asm volatile("cp.async.commit_group;");                                          \
    } while (0)

    STAGE_CHUNK(0);
    STAGE_CHUNK(1);

    for (int c = 0; c < NCHUNK; c++) {
        if (c + 1 < NCHUNK) asm volatile("cp.async.wait_group 1;");
        else                asm volatile("cp.async.wait_group 0;");
        __syncthreads();
        if (c + 2 < NCHUNK) STAGE_CHUNK(c + 2);

        const uint32_t Ab = sb + SM_TILE0 + (c % NS) * STAGE_BYTES;
        const uint32_t Bb = Ab + A_BYTES;
#pragma unroll
        for (int ks = 0; ks < 4; ks++) {
            const int k0 = ks * 16;
            uint32_t a[2][4];
#pragma unroll
            for (int mf = 0; mf < 2; mf++) {
                int r = warp_m * 32 + mf * 16 + lm_r;
                ldmatrix_x4(a[mf], Ab + SWZ(r * 128 + (k0 + lm_k) * 2));
            }
            uint32_t b[4][4];
#pragma unroll
            for (int p = 0; p < 4; p++) {
                int n = warp_n * 64 + p * 16 + lm_r;
                ldmatrix_x4(b[p], Bb + SWZ(n * 128 + (k0 + lm_k) * 2));
            }
#pragma unroll
            for (int mf = 0; mf < 2; mf++)
#pragma unroll
                for (int nf = 0; nf < 8; nf++)
                    mma16816(acc[mf][nf], a[mf], b[nf >> 1][nf & 1], b[nf >> 1][(nf & 1) + 2]);
        }
    }

    // ---------- row-side argmin (band J) ----------
    {
        float bva[2], bvb[2];
        int   bia[2], bib[2];
#pragma unroll
        for (int mf = 0; mf < 2; mf++) { bva[mf] = 1e30f; bvb[mf] = 1e30f; bia[mf] = 0; bib[mf] = 0; }

#pragma unroll
        for (int mf = 0; mf < 2; mf++) {
            const int ra = row0 + warp_m * 32 + mf * 16 + (lane >> 2);
            const int rb = ra + 8;
#pragma unroll
            for (int nf = 0; nf < 8; nf++) {
                const int lc = warp_n * 64 + nf * 8 + (lane & 3) * 2;
                const float sq0 = sSqC[lc], sq1 = sSqC[lc + 1];
                const int c0 = col0 + lc;
                float d0 = sq0 - 2.f * acc[mf][nf][0];
                float d1 = sq1 - 2.f * acc[mf][nf][1];
                float d2 = sq0 - 2.f * acc[mf][nf][2];
                float d3 = sq1 - 2.f * acc[mf][nf][3];
                if (c0 != ra && (d0 < bva[mf] || (d0 == bva[mf] && c0 < bia[mf]))) { bva[mf] = d0; bia[mf] = c0; }
                if (c0 + 1 != ra && (d1 < bva[mf] || (d1 == bva[mf] && c0 + 1 < bia[mf]))) { bva[mf] = d1; bia[mf] = c0 + 1; }
                if (c0 != rb && (d2 < bvb[mf] || (d2 == bvb[mf] && c0 < bib[mf]))) { bvb[mf] = d2; bib[mf] = c0; }
                if (c0 + 1 != rb && (d3 < bvb[mf] || (d3 == bvb[mf] && c0 + 1 < bib[mf]))) { bvb[mf] = d3; bib[mf] = c0 + 1; }
            }
        }
#pragma unroll
        for (int off = 1; off <= 2; off <<= 1) {
#pragma unroll
            for (int mf = 0; mf < 2; mf++) {
                float v = __shfl_xor_sync(0xffffffffu, bva[mf], off);
                int   i2 = __shfl_xor_sync(0xffffffffu, bia[mf], off);
                if (v < bva[mf] || (v == bva[mf] && i2 < bia[mf])) { bva[mf] = v; bia[mf] = i2; }
                v  = __shfl_xor_sync(0xffffffffu, bvb[mf], off);
                i2 = __shfl_xor_sync(0xffffffffu, bib[mf], off);
                if (v < bvb[mf] || (v == bvb[mf] && i2 < bib[mf])) { bvb[mf] = v; bib[mf] = i2; }
            }
        }
        if ((lane & 3) == 0) {
#pragma unroll
            for (int mf = 0; mf < 2; mf++) {
                int rt = warp_m * 32 + mf * 16 + (lane >> 2);
                redV[warp_n * 128 + rt] = bva[mf];      redI[warp_n * 128 + rt] = bia[mf];
                redV[warp_n * 128 + rt + 8] = bvb[mf];  redI[warp_n * 128 + rt + 8] = bib[mf];
            }
        }
    }

    // ---------- col-side argmin (band I) ----------
    if (!diag) {
#pragma unroll
        for (int nf = 0; nf < 8; nf++) {
#pragma unroll
            for (int e = 0; e < 2; e++) {
                float bv = 1e30f;
                int bi = 0;
#pragma unroll
                for (int mf = 0; mf < 2; mf++) {
                    int rla = warp_m * 32 + mf * 16 + (lane >> 2);
                    float da = sSqR[rla] - 2.f * acc[mf][nf][e];
                    float db = sSqR[rla + 8] - 2.f * acc[mf][nf][e + 2];
                    int ga = row0 + rla, gb = ga + 8;
                    if (da < bv || (da == bv && ga < bi)) { bv = da; bi = ga; }
                    if (db < bv || (db == bv && gb < bi)) { bv = db; bi = gb; }
                }
#pragma unroll
                for (int off = 4; off <= 16; off <<= 1) {
                    float v = __shfl_xor_sync(0xffffffffu, bv, off);
                    int i2  = __shfl_xor_sync(0xffffffffu, bi, off);
                    if (v < bv || (v == bv && i2 < bi)) { bv = v; bi = i2; }
                }
                if (lane < 4) {
                    int cl = warp_n * 64 + nf * 8 + lane * 2 + e;
                    colV[warp_m * 128 + cl] = bv;
                    colI[warp_m * 128 + cl] = bi;
                }
            }
        }
    }
    __syncthreads();

    if (tid < 128) {
        float bv = redV[tid]; int bi = redI[tid];
        float v = redV[128 + tid]; int i2 = redI[128 + tid];
        if (v < bv || (v == bv && i2 < bi)) { bv = v; bi = i2; }
        g_pmin[J * NPTS + row0 + tid] = bv;
        g_pidx[J * NPTS + row0 + tid] = bi;
        if (!diag) {
            bv = colV[tid]; bi = colI[tid];
#pragma unroll
            for (int wm = 1; wm < 4; wm++) {
                v = colV[wm * 128 + tid]; i2 = colI[wm * 128 + tid];
                if (v < bv || (v == bv && i2 < bi)) { bv = v; bi = i2; }
            }
            g_pmin[I * NPTS + col0 + tid] = bv;
            g_pidx[I * NPTS + col0 + tid] = bi;
        }
    }
}

// ---------------- kernel 3: reduce the 64 band partial argmins ----------------
__global__ void reduce_argmin_kernel() {
    int i = blockIdx.x * 256 + threadIdx.x;
    if (i >= NPTS) return;
    float bv = 1e30f;
    int bi = 0;
    for (int s = 0; s < NBAND; s++) {
        float v = g_pmin[s * NPTS + i];
        int id2 = g_pidx[s * NPTS + i];
        if (v < bv || (v == bv && id2 < bi)) { bv = v; bi = id2; }
    }
    g_closest[i] = bi;
}

// ---------------- kernel Z1: Z1 = xs @ W1^T + b1  (8192x64, K=512) ----------------
// Tiled SIMT GEMM: CTA 64 rows x 64 outs, 256 threads, 4x4 per thread, BK=64.
__global__ __launch_bounds__(256, 2) void z1_gemm(
    const float* __restrict__ xs, const float* __restrict__ W1,
    const float* __restrict__ b1) {
    __shared__ float As[64][68];  // [k][r]
    __shared__ float Bs[64][68];  // [k][o]
    const int tid = threadIdx.x;
    const int tx = tid & 15, ty = tid >> 4;
    const int row0 = blockIdx.x * 64;

    float acc[4][4];
#pragma unroll
    for (int m = 0; m < 4; m++)
#pragma unroll
        for (int n = 0; n < 4; n++) acc[m][n] = 0.f;

    for (int kb = 0; kb < DIM; kb += 64) {
#pragma unroll
        for (int l = 0; l < 4; l++) {
            int e = tid + l * 256;            // 1024 float4 per tensor
            int r = e >> 4, k4 = (e & 15) * 4;
            float4 va = *(const float4*)&xs[(size_t)(row0 + r) * DIM + kb + k4];
            As[k4 + 0][r] = va.x; As[k4 + 1][r] = va.y; As[k4 + 2][r] = va.z; As[k4 + 3][r] = va.w;
            float4 vb = *(const float4*)&W1[(size_t)r * DIM + kb + k4];
            Bs[k4 + 0][r] = vb.x; Bs[k4 + 1][r] = vb.y; Bs[k4 + 2][r] = vb.z; Bs[k4 + 3][r] = vb.w;
        }
        __syncthreads();
#pragma unroll
        for (int k = 0; k < 64; k++) {
            float4 a = *(const float4*)&As[k][tx * 4];
            float4 b = *(const float4*)&Bs[k][ty * 4];
            float ar[4] = {a.x, a.y, a.z, a.w};
            float br[4] = {b.x, b.y, b.z, b.w};
#pragma unroll
            for (int m = 0; m < 4; m++)
#pragma unroll
                for (int n = 0; n < 4; n++) acc[m][n] += ar[m] * br[n];
        }
        __syncthreads();
    }
#pragma unroll
    for (int m = 0; m < 4; m++)
#pragma unroll
        for (int n = 0; n < 4; n++) {
            int o = ty * 4 + n;
            g_Z1[(size_t)(row0 + tx * 4 + m) * 64 + o] = acc[m][n] + __ldg(&b1[o]);
        }
}

// ---------------- kernel Z2: Z2 = W2 @ relu(Z1) + b2  (8192x32) ----------------
__global__ __launch_bounds__(256, 4) void z2_kernel(
    const float* __restrict__ W2, const float* __restrict__ b2) {
    __shared__ float sW2t[64 * 32];
    __shared__ float sA[8][64];
    const int tid = threadIdx.x;
    for (int i = tid; i < 32 * 64; i += 256) {
        int o = i >> 6, k = i & 63;
        sW2t[k * 32 + o] = W2[i];
    }
    __syncthreads();
    const int warp = tid >> 5, lane = tid & 31;
    const int row = blockIdx.x * 8 + warp;
    float* a1 = sA[warp];
    a1[lane] = fmaxf(g_Z1[(size_t)row * 64 + lane], 0.f);
    a1[lane + 32] = fmaxf(g_Z1[(size_t)row * 64 + lane + 32], 0.f);
    __syncwarp();
    float z = __ldg(&b2[lane]);
#pragma unroll
    for (int k = 0; k < 64; k++) z += sW2t[k * 32 + lane] * a1[k];
    g_Z2[(size_t)row * 32 + lane] = z;
}

// ---------------- kernel PAIR: masked JVP encoder + decoder front ----------------
// z = W3(m2 o (W2(m1 o Z1[i]) + b2)) + b3, masks m1,m2 from Z1[j], Z2[j].
// Then h1 = relu(D1 z + d1), h2 = relu(D2 h1 + d2) -> g_h2. zs written to out.
__global__ __launch_bounds__(256, 4) void pair_kernel(
    const float* __restrict__ W2, const float* __restrict__ b2,
    const float* __restrict__ W3, const float* __restrict__ b3,
    const float* __restrict__ D1, const float* __restrict__ d1,
    const float* __restrict__ D2, const float* __restrict__ d2,
    float* __restrict__ out) {
    __shared__ float sW2t[64 * 32];
    __shared__ float sW3t[32 * 32];
    __shared__ float sD1t[32 * 32];
    __shared__ float sD2t[32 * 64];
    __shared__ float sScr[8][160];
    const int tid = threadIdx.x;
    for (int i = tid; i < 32 * 64; i += 256) { int o = i >> 6, k = i & 63; sW2t[k * 32 + o] = W2[i]; }
    for (int i = tid; i < 32 * 32; i += 256) { int o = i >> 5, k = i & 31; sW3t[k * 32 + o] = W3[i]; sD1t[k * 32 + o] = D1[i]; }
    for (int i = tid; i < 64 * 32; i += 256) { int o = i >> 5, k = i & 31; sD2t[k * 64 + o] = D2[i]; }
    __syncthreads();

    const int warp = tid >> 5, lane = tid & 31;
    const int row = blockIdx.x * 8 + warp;
    float* sU  = sScr[warp];        // 64: masked u1
    float* sU2 = sU + 64;           // 32: masked u2
    float* sZ  = sU + 96;           // 32: z
    float* sH1 = sU + 128;          // 32: h1

    const int j = g_closest[row];
#pragma unroll
    for (int h = 0; h < 2; h++) {
        int k = lane + 32 * h;
        float zi = g_Z1[(size_t)row * 64 + k];
        float zj = g_Z1[(size_t)j * 64 + k];
        sU[k] = (zj > 0.f) ? zi : 0.f;
    }
    __syncwarp();
    {
        float u2 = __ldg(&b2[lane]);
#pragma unroll
        for (int k = 0; k < 64; k++) u2 += sW2t[k * 32 + lane] * sU[k];
        float z2j = g_Z2[(size_t)j * 32 + lane];
        sU2[lane] = (z2j > 0.f) ? u2 : 0.f;
    }
    __syncwarp();
    {
        float z = __ldg(&b3[lane]);
#pragma unroll
        for (int k = 0; k < 32; k++) z += sW3t[k * 32 + lane] * sU2[k];
        sZ[lane] = z;
        out[(size_t)NPTS * DIM + (size_t)row * 32 + lane] = z;
    }
    __syncwarp();
    {
        float h = __ldg(&d1[lane]);
#pragma unroll
        for (int k = 0; k < 32; k++) h += sD1t[k * 32 + lane] * sZ[k];
        sH1[lane] = fmaxf(h, 0.f);
    }
    __syncwarp();
#pragma unroll
    for (int hh = 0; hh < 2; hh++) {
        int o = lane + 32 * hh;
        float h = __ldg(&d2[o]);
#pragma unroll
        for (int k = 0; k < 32; k++) h += sD2t[k * 64 + o] * sH1[k];
        g_h2[(size_t)row * 64 + o] = fmaxf(h, 0.f);
    }
}

// ---------------- kernel DEC: x_hat = h2 @ D3^T + d3  (8192x512, K=64) ----------------
// CTA 128 rows x 128 cols, 256 threads, 8x8 per thread, single K pass.
#define DEC_SMEM (2 * 64 * 132 * 4)
__global__ __launch_bounds__(256, 2) void dec_gemm(
    const float* __restrict__ D3, const float* __restrict__ d3,
    float* __restrict__ out) {
    extern __shared__ float ds[];
    float (*As)[132] = (float(*)[132])ds;           // [k][r]
    float (*Bs)[132] = (float(*)[132])(ds + 64 * 132);  // [k][n]
    const int tid = threadIdx.x;
    const int tx = tid & 15, ty = tid >> 4;
    const int row0 = blockIdx.x * 128;
    const int col0 = blockIdx.y * 128;

#pragma unroll
    for (int l = 0; l < 8; l++) {
        int e = tid + l * 256;  // 2048 float4 each
        int r = e >> 4, k4 = (e & 15) * 4;
        float4 va = *(const float4*)&g_h2[(size_t)(row0 + r) * 64 + k4];
        As[k4 + 0][r] = va.x; As[k4 + 1][r] = va.y; As[k4 + 2][r] = va.z; As[k4 + 3][r] = va.w;
        float4 vb = *(const float4*)&D3[(size_t)(col0 + r) * 64 + k4];
        Bs[k4 + 0][r] = vb.x; Bs[k4 + 1][r] = vb.y; Bs[k4 + 2][r] = vb.z; Bs[k4 + 3][r] = vb.w;
    }
    __syncthreads();

    float acc[8][8];
#pragma unroll
    for (int m = 0; m < 8; m++)
#pragma unroll
        for (int n = 0; n < 8; n++) acc[m][n] = 0.f;

#pragma unroll
    for (int k = 0; k < 64; k++) {
        float ar[8], br[8];
        float4 a0 = *(const float4*)&As[k][tx * 8];
        float4 a1 = *(const float4*)&As[k][tx * 8 + 4];
        ar[0] = a0.x; ar[1] = a0.y; ar[2] = a0.z; ar[3] = a0.w;
        ar[4] = a1.x; ar[5] = a1.y; ar[6] = a1.z; ar[7] = a1.w;
        float4 b0 = *(const float4*)&Bs[k][ty * 8];
        float4 b1 = *(const float4*)&Bs[k][ty * 8 + 4];
        br[0] = b0.x; br[1] = b0.y; br[2] = b0.z; br[3] = b0.w;
        br[4] = b1.x; br[5] = b1.y; br[6] = b1.z; br[7] = b1.w;
#pragma unroll
        for (int m = 0; m < 8; m++)
#pragma unroll
            for (int n = 0; n < 8; n++) acc[m][n] += ar[m] * br[n];
    }

#pragma unroll
    for (int m = 0; m < 8; m++) {
        int r = row0 + tx * 8 + m;
#pragma unroll
        for (int n = 0; n < 8; n++) {
            int cc = col0 + ty * 8 + n;
            out[(size_t)r * DIM + cc] = acc[m][n] + __ldg(&d3[cc]);
        }
    }
}

// ---------------- launch ----------------
extern "C" void kernel_launch(void* const* d_in, const int* in_sizes, int n_in,
                              void* d_out, int out_size) {
    const float* xs = (const float*)d_in[0];
    const float* W1 = (const float*)d_in[1];
    const float* b1 = (const float*)d_in[2];
    const float* W2 = (const float*)d_in[3];
    const float* b2 = (const float*)d_in[4];
    const float* W3 = (const float*)d_in[5];
    const float* b3 = (const float*)d_in[6];
    const float* D1 = (const float*)d_in[7];
    const float* d1 = (const float*)d_in[8];
    const float* D2 = (const float*)d_in[9];
    const float* d2 = (const float*)d_in[10];
    const float* D3 = (const float*)d_in[11];
    const float* d3 = (const float*)d_in[12];
    float* out = (float*)d_out;

    convert_kernel<<<NPTS * DIM / 256, 256>>>(xs);
    row_norms_kernel<<<NPTS / 8, 256>>>(xs);

    cudaFuncSetAttribute(gram_argmin_tri, cudaFuncAttributeMaxDynamicSharedMemorySize, SMEM_GEMM);
    const int npairs = NBLK * (NBLK + 1) / 2;  // 2080
    gram_argmin_tri<<<npairs, 256, SMEM_GEMM>>>();

    reduce_argmin_kernel<<<NPTS / 256, 256>>>();

    z1_gemm<<<NPTS / 64, 256>>>(xs, W1, b1);
    z2_kernel<<<NPTS / 8, 256>>>(W2, b2);
    pair_kernel<<<NPTS / 8, 256>>>(W2, b2, W3, b3, D1, d1, D2, d2, out);

    cudaFuncSetAttribute(dec_gemm, cudaFuncAttributeMaxDynamicSharedMemorySize, DEC_SMEM);
    dim3 gdec(NPTS / 128, 4);
    dec_gemm<<<gdec, 256, DEC_SMEM>>>(D3, d3, out);
}

// round 10
// speedup vs baseline: 5.7243x; 1.1358x over previous
#include <cuda_runtime.h>
#include <cuda_bf16.h>
#include <cuda_fp16.h>
#include <cstdint>
#include <cmath>

#define NPTS 8192
#define DIM  512
#define NBLK 64

// ---------------- device scratch (no allocations allowed) ----------------
__device__ float g_sq[NPTS];
__device__ float g_hin[NPTS];
__device__ float g_lon[NPTS];
__device__ int   g_HmaxBits;   // idempotent atomicMax across replays
__device__ int   g_LmaxBits;
__device__ int   g_closest[NPTS];
__device__ __nv_bfloat16 g_xb[(size_t)NPTS * 512];      // hi(bf16) per row
__device__ __half g_c[(size_t)NPTS * NPTS];             // filtered distances (fp16)
__device__ float g_Z1[NPTS * 64];
__device__ float g_Z2[NPTS * 32];
__device__ float g_h2[NPTS * 64];

// ---------------- helpers ----------------
__device__ __forceinline__ uint32_t smem_u32(const void* p) {
    uint32_t a;
    asm("{ .reg .u64 t; cvta.to.shared.u64 t, %1; cvt.u32.u64 %0, t; }" : "=r"(a) : "l"(p));
    return a;
}
#define SWZ(b) ((b) ^ (((b) >> 3) & 0x70))

__device__ __forceinline__ void cp_async16(uint32_t dst, const void* src) {
    asm volatile("cp.async.cg.shared.global [%0], [%1], 16;" :: "r"(dst), "l"(src));
}
__device__ __forceinline__ void ldmatrix_x4(uint32_t* r, uint32_t addr) {
    asm volatile("ldmatrix.sync.aligned.m8n8.x4.shared.b16 {%0,%1,%2,%3}, [%4];"
                 : "=r"(r[0]), "=r"(r[1]), "=r"(r[2]), "=r"(r[3]) : "r"(addr));
}
__device__ __forceinline__ void mma16816(float* d, const uint32_t* a, uint32_t b0, uint32_t b1) {
    asm volatile(
        "mma.sync.aligned.m16n8k16.row.col.f32.bf16.bf16.f32 "
        "{%0,%1,%2,%3}, {%4,%5,%6,%7}, {%8,%9}, {%0,%1,%2,%3};"
        : "+f"(d[0]), "+f"(d[1]), "+f"(d[2]), "+f"(d[3])
        : "r"(a[0]), "r"(a[1]), "r"(a[2]), "r"(a[3]), "r"(b0), "r"(b1));
}

// ---------------- kernel 0: convert + norms (fused) ----------------
// warp per row: hi = bf16(x), lo = x - hi; store hi; exact fp32 norms.
__global__ __launch_bounds__(256, 4) void convert_norms_kernel(const float* __restrict__ xs) {
    int warp = threadIdx.x >> 5, lane = threadIdx.x & 31;
    int row = blockIdx.x * 8 + warp;
    const float* p = xs + (size_t)row * DIM;
    float sq = 0.f, h2s = 0.f, l2s = 0.f;
#pragma unroll
    for (int t = 0; t < 16; t++) {
        float x = p[lane + 32 * t];
        __nv_bfloat16 hb = __float2bfloat16(x);
        float hf = __bfloat162float(hb);
        float lf = x - hf;
        g_xb[(size_t)row * 512 + lane + 32 * t] = hb;
        sq += x * x;
        h2s += hf * hf;
        l2s += lf * lf;
    }
#pragma unroll
    for (int off = 16; off; off >>= 1) {
        sq  += __shfl_xor_sync(0xffffffffu, sq, off);
        h2s += __shfl_xor_sync(0xffffffffu, h2s, off);
        l2s += __shfl_xor_sync(0xffffffffu, l2s, off);
    }
    if (lane == 0) {
        g_sq[row] = sq;
        float hn = sqrtf(h2s), ln = sqrtf(l2s);
        g_hin[row] = hn;
        g_lon[row] = ln;
        atomicMax(&g_HmaxBits, __float_as_int(hn));
        atomicMax(&g_LmaxBits, __float_as_int(ln));
    }
}

// ---------------- kernel 1: triangular HMMA gram-light (hi.hi, K=512) ----------------
// CTA tile 128x128 over block pairs (I<=J). Epilogue stores c = sq_j - 2dot - 1024
// as fp16: direct for (I rows x J cols), smem-transposed for (J rows x I cols).
#define TM 128
#define TN 128
#define KB 64
#define NCHUNK 8
#define NS 3
#define A_BYTES (TM * 128)
#define B_BYTES (TN * 128)
#define STAGE_BYTES (A_BYTES + B_BYTES)
#define SM_SQC 0
#define SM_SQR 512
#define SM_TILE0 1024
#define SMEM_GEMM (SM_TILE0 + NS * STAGE_BYTES)
#define TRANS_STRIDE 136   // halves; 272B rows, 16B aligned, bank-spread

__device__ __forceinline__ int tri_cum(int I) { return 64 * I - (I * (I - 1)) / 2; }

__global__ __launch_bounds__(256, 2) void gram_store_tri() {
    extern __shared__ char smem[];
    const uint32_t sb = smem_u32(smem);
    float* sSqC = (float*)(smem + SM_SQC);
    float* sSqR = (float*)(smem + SM_SQR);

    const int tid = threadIdx.x;
    const int lane = tid & 31, wid = tid >> 5;
    const int warp_m = wid & 3, warp_n = wid >> 2;   // 4 x 2

    const int t = blockIdx.x;
    int I = (int)((129.0 - sqrt(129.0 * 129.0 - 8.0 * (double)t)) * 0.5);
    while (tri_cum(I + 1) <= t) I++;
    while (tri_cum(I) > t) I--;
    const int J = I + (t - tri_cum(I));
    const int row0 = I * TM;
    const int col0 = J * TN;
    const bool diag = (I == J);

    if (tid < 128) {
        sSqC[tid] = g_sq[col0 + tid];
        sSqR[tid] = g_sq[row0 + tid];
    }

    float acc[2][8][4];
#pragma unroll
    for (int mf = 0; mf < 2; mf++)
#pragma unroll
        for (int nf = 0; nf < 8; nf++)
#pragma unroll
            for (int e = 0; e < 4; e++) acc[mf][nf][e] = 0.f;

    const int lm_r = lane & 15;
    const int lm_k = (lane >> 4) * 8;

    const __nv_bfloat16* gXr = g_xb + (size_t)row0 * 512;
    const __nv_bfloat16* gXc = g_xb + (size_t)col0 * 512;

#define STAGE_CHUNK(cc)                                                                 \
    do {                                                                                \
        const int _st = (cc) % NS;                                                      \
        const uint32_t _sa = sb + SM_TILE0 + _st * STAGE_BYTES;                         \
        const uint32_t _sb2 = _sa + A_BYTES;                                            \
        const __nv_bfloat16* _gA = gXr + (cc) * KB;                                     \
        const __nv_bfloat16* _gB = gXc + (cc) * KB;                                     \
        _Pragma("unroll")                                                               \
        for (int _it = 0; _it < 4; _it++) {                                             \
            int _e = tid + _it * 256, _r = _e >> 3, _s = _e & 7;                        \
            cp_async16(_sa + SWZ(_r * 128 + _s * 16), _gA + (size_t)_r * 512 + _s * 8); \
            cp_async16(_sb2 + SWZ(_r * 128 + _s * 16), _gB + (size_t)_r * 512 + _s * 8);\
        }                                                                               \
        asm volatile("cp.async.commit_group;");                                         \
    } while (0)

    STAGE_CHUNK(0);
    STAGE_CHUNK(1);

    for (int c = 0; c < NCHUNK; c++) {
        if (c + 1 < NCHUNK) asm volatile("cp.async.wait_group 1;");
        else                asm volatile("cp.async.wait_group 0;");
        __syncthreads();
        if (c + 2 < NCHUNK) STAGE_CHUNK(c + 2);

        const uint32_t Ab = sb + SM_TILE0 + (c % NS) * STAGE_BYTES;
        const uint32_t Bb = Ab + A_BYTES;
#pragma unroll
        for (int ks = 0; ks < 4; ks++) {
            const int k0 = ks * 16;
            uint32_t a[2][4];
#pragma unroll
            for (int mf = 0; mf < 2; mf++) {
                int r = warp_m * 32 + mf * 16 + lm_r;
                ldmatrix_x4(a[mf], Ab + SWZ(r * 128 + (k0 + lm_k) * 2));
            }
            uint32_t b[4][4];
#pragma unroll
            for (int p = 0; p < 4; p++) {
                int n = warp_n * 64 + p * 16 + lm_r;
                ldmatrix_x4(b[p], Bb + SWZ(n * 128 + (k0 + lm_k) * 2));
            }
#pragma unroll
            for (int mf = 0; mf < 2; mf++)
#pragma unroll
                for (int nf = 0; nf < 8; nf++)
                    mma16816(acc[mf][nf], a[mf], b[nf >> 1][nf & 1], b[nf >> 1][(nf & 1) + 2]);
        }
    }

    __syncthreads();  // all LDSM done; safe to reuse stage smem for transpose
    __half* trans = (__half*)(smem + SM_TILE0);

#pragma unroll
    for (int mf = 0; mf < 2; mf++) {
        const int ra = warp_m * 32 + mf * 16 + (lane >> 2);
        const int rb = ra + 8;
        const float sqa = sSqR[ra], sqb = sSqR[rb];
#pragma unroll
        for (int nf = 0; nf < 8; nf++) {
            const int lc = warp_n * 64 + nf * 8 + (lane & 3) * 2;
            // direct: c(row0+ra, col0+lc..lc+1), c(row0+rb, ...)
            float c00 = sSqC[lc]     - 2.f * acc[mf][nf][0] - 1024.f;
            float c01 = sSqC[lc + 1] - 2.f * acc[mf][nf][1] - 1024.f;
            float c10 = sSqC[lc]     - 2.f * acc[mf][nf][2] - 1024.f;
            float c11 = sSqC[lc + 1] - 2.f * acc[mf][nf][3] - 1024.f;
            *(__half2*)&g_c[(size_t)(row0 + ra) * NPTS + col0 + lc] = __floats2half2_rn(c00, c01);
            *(__half2*)&g_c[(size_t)(row0 + rb) * NPTS + col0 + lc] = __floats2half2_rn(c10, c11);
            if (!diag) {
                // transposed values: c(col0+lc, row0+ra) = sq[row] - 2dot - 1024
                trans[lc * TRANS_STRIDE + ra]       = __float2half_rn(sqa - 2.f * acc[mf][nf][0] - 1024.f);
                trans[(lc + 1) * TRANS_STRIDE + ra] = __float2half_rn(sqa - 2.f * acc[mf][nf][1] - 1024.f);
                trans[lc * TRANS_STRIDE + rb]       = __float2half_rn(sqb - 2.f * acc[mf][nf][2] - 1024.f);
                trans[(lc + 1) * TRANS_STRIDE + rb] = __float2half_rn(sqb - 2.f * acc[mf][nf][3] - 1024.f);
            }
        }
    }
    if (!diag) {
        __syncthreads();
        // coalesced copy out: 128 rows x 128 halves (16 uint4 per row)
#pragma unroll
        for (int it = 0; it < 8; it++) {
            int e = tid + it * 256;
            int r = e >> 4, s = e & 15;
            ((uint4*)(g_c + (size_t)(col0 + r) * NPTS + row0))[s] =
                ((const uint4*)(trans + r * TRANS_STRIDE))[s];
        }
    }
}

// ---------------- kernel 2: scan + exact recheck ----------------
// Block per row: min over fp16 c, window threshold (deterministic C-S bound),
// exact fp32 dots for flagged cols, true argmin with low-index tiebreak.
__global__ __launch_bounds__(256, 4) void scan_kernel(const float* __restrict__ xs) {
    __shared__ float sX[512];
    __shared__ float wMin[8];
    __shared__ float wBD[8];
    __shared__ int   wBJ[8];
    const int row = blockIdx.x;
    const int tid = threadIdx.x, lane = tid & 31, wid = tid >> 5;
    const __half2* crow = (const __half2*)(g_c + (size_t)row * NPTS);

    // phase A: row min (skip diagonal)
    float cmin = 1e30f;
#pragma unroll 4
    for (int it = 0; it < 16; it++) {
        int p = tid + it * 256;
        float2 f = __half22float2(crow[p]);
        int j0 = 2 * p;
        if (j0 != row && f.x < cmin) cmin = f.x;
        if (j0 + 1 != row && f.y < cmin) cmin = f.y;
    }
#pragma unroll
    for (int off = 16; off; off >>= 1) cmin = fminf(cmin, __shfl_xor_sync(0xffffffffu, cmin, off));
    if (lane == 0) wMin[wid] = cmin;
    // load xs row while waiting
    for (int i = tid; i < 512; i += 256) sX[i] = xs[(size_t)row * DIM + i];
    __syncthreads();
    float m = wMin[0];
#pragma unroll
    for (int w = 1; w < 8; w++) m = fminf(m, wMin[w]);

    const float Hmax = __int_as_float(g_HmaxBits);
    const float Lmax = __int_as_float(g_LmaxBits);
    const float B = g_hin[row] * Lmax + g_lon[row] * (Hmax + Lmax);
    const float th = m + 4.f * B + 3.0f;
    const float sqi = g_sq[row];

    float bd = 1e30f;
    int bj = NPTS;
    for (int it = 0; it < 16; it++) {
        int p = tid + it * 256;
        float2 f = __half22float2(crow[p]);
        int j0 = 2 * p;
#pragma unroll
        for (int e = 0; e < 2; e++) {
            float cv = (e == 0) ? f.x : f.y;
            unsigned msk = __ballot_sync(0xffffffffu, cv < th && (j0 + e) != row);
            while (msk) {
                int src = __ffs(msk) - 1;
                msk &= msk - 1;
                int j = 2 * ((wid * 32 + src) + it * 256) + e;
                const float* xj = xs + (size_t)j * DIM;
                float s = 0.f;
#pragma unroll
                for (int tt = 0; tt < 16; tt++) s += sX[lane + 32 * tt] * xj[lane + 32 * tt];
#pragma unroll
                for (int off = 16; off; off >>= 1) s += __shfl_xor_sync(0xffffffffu, s, off);
                float d = sqi + g_sq[j] - 2.f * s;
                if (d < bd || (d == bd && j < bj)) { bd = d; bj = j; }
            }
        }
    }
    if (lane == 0) { wBD[wid] = bd; wBJ[wid] = bj; }
    __syncthreads();
    if (tid == 0) {
        float fb = wBD[0]; int fj = wBJ[0];
#pragma unroll
        for (int w = 1; w < 8; w++) {
            if (wBD[w] < fb || (wBD[w] == fb && wBJ[w] < fj)) { fb = wBD[w]; fj = wBJ[w]; }
        }
        g_closest[row] = fj;
    }
}

// ---------------- kernel Z1: Z1 = xs @ W1^T + b1 ----------------
__global__ __launch_bounds__(256, 2) void z1_gemm(
    const float* __restrict__ xs, const float* __restrict__ W1,
    const float* __restrict__ b1) {
    __shared__ float As[64][68];
    __shared__ float Bs[64][68];
    const int tid = threadIdx.x;
    const int tx = tid & 15, ty = tid >> 4;
    const int row0 = blockIdx.x * 64;

    float acc[4][4];
#pragma unroll
    for (int m = 0; m < 4; m++)
#pragma unroll
        for (int n = 0; n < 4; n++) acc[m][n] = 0.f;

    for (int kb = 0; kb < DIM; kb += 64) {
#pragma unroll
        for (int l = 0; l < 4; l++) {
            int e = tid + l * 256;
            int r = e >> 4, k4 = (e & 15) * 4;
            float4 va = *(const float4*)&xs[(size_t)(row0 + r) * DIM + kb + k4];
            As[k4 + 0][r] = va.x; As[k4 + 1][r] = va.y; As[k4 + 2][r] = va.z; As[k4 + 3][r] = va.w;
            float4 vb = *(const float4*)&W1[(size_t)r * DIM + kb + k4];
            Bs[k4 + 0][r] = vb.x; Bs[k4 + 1][r] = vb.y; Bs[k4 + 2][r] = vb.z; Bs[k4 + 3][r] = vb.w;
        }
        __syncthreads();
#pragma unroll
        for (int k = 0; k < 64; k++) {
            float4 a = *(const float4*)&As[k][tx * 4];
            float4 b = *(const float4*)&Bs[k][ty * 4];
            float ar[4] = {a.x, a.y, a.z, a.w};
            float br[4] = {b.x, b.y, b.z, b.w};
#pragma unroll
            for (int m = 0; m < 4; m++)
#pragma unroll
                for (int n = 0; n < 4; n++) acc[m][n] += ar[m] * br[n];
        }
        __syncthreads();
    }
#pragma unroll
    for (int m = 0; m < 4; m++)
#pragma unroll
        for (int n = 0; n < 4; n++) {
            int o = ty * 4 + n;
            g_Z1[(size_t)(row0 + tx * 4 + m) * 64 + o] = acc[m][n] + __ldg(&b1[o]);
        }
}

// ---------------- kernel Z2: Z2 = W2 @ relu(Z1) + b2 ----------------
__global__ __launch_bounds__(256, 4) void z2_kernel(
    const float* __restrict__ W2, const float* __restrict__ b2) {
    __shared__ float sW2t[64 * 32];
    __shared__ float sA[8][64];
    const int tid = threadIdx.x;
    for (int i = tid; i < 32 * 64; i += 256) {
        int o = i >> 6, k = i & 63;
        sW2t[k * 32 + o] = W2[i];
    }
    __syncthreads();
    const int warp = tid >> 5, lane = tid & 31;
    const int row = blockIdx.x * 8 + warp;
    float* a1 = sA[warp];
    a1[lane] = fmaxf(g_Z1[(size_t)row * 64 + lane], 0.f);
    a1[lane + 32] = fmaxf(g_Z1[(size_t)row * 64 + lane + 32], 0.f);
    __syncwarp();
    float z = __ldg(&b2[lane]);
#pragma unroll
    for (int k = 0; k < 64; k++) z += sW2t[k * 32 + lane] * a1[k];
    g_Z2[(size_t)row * 32 + lane] = z;
}

// ---------------- kernel PAIR: masked JVP encoder + decoder front ----------------
__global__ __launch_bounds__(256, 4) void pair_kernel(
    const float* __restrict__ W2, const float* __restrict__ b2,
    const float* __restrict__ W3, const float* __restrict__ b3,
    const float* __restrict__ D1, const float* __restrict__ d1,
    const float* __restrict__ D2, const float* __restrict__ d2,
    float* __restrict__ out) {
    __shared__ float sW2t[64 * 32];
    __shared__ float sW3t[32 * 32];
    __shared__ float sD1t[32 * 32];
    __shared__ float sD2t[32 * 64];
    __shared__ float sScr[8][160];
    const int tid = threadIdx.x;
    for (int i = tid; i < 32 * 64; i += 256) { int o = i >> 6, k = i & 63; sW2t[k * 32 + o] = W2[i]; }
    for (int i = tid; i < 32 * 32; i += 256) { int o = i >> 5, k = i & 31; sW3t[k * 32 + o] = W3[i]; sD1t[k * 32 + o] = D1[i]; }
    for (int i = tid; i < 64 * 32; i += 256) { int o = i >> 5, k = i & 31; sD2t[k * 64 + o] = D2[i]; }
    __syncthreads();

    const int warp = tid >> 5, lane = tid & 31;
    const int row = blockIdx.x * 8 + warp;
    float* sU  = sScr[warp];
    float* sU2 = sU + 64;
    float* sZ  = sU + 96;
    float* sH1 = sU + 128;

    const int j = g_closest[row];
#pragma unroll
    for (int h = 0; h < 2; h++) {
        int k = lane + 32 * h;
        float zi = g_Z1[(size_t)row * 64 + k];
        float zj = g_Z1[(size_t)j * 64 + k];
        sU[k] = (zj > 0.f) ? zi : 0.f;
    }
    __syncwarp();
    {
        float u2 = __ldg(&b2[lane]);
#pragma unroll
        for (int k = 0; k < 64; k++) u2 += sW2t[k * 32 + lane] * sU[k];
        float z2j = g_Z2[(size_t)j * 32 + lane];
        sU2[lane] = (z2j > 0.f) ? u2 : 0.f;
    }
    __syncwarp();
    {
        float z = __ldg(&b3[lane]);
#pragma unroll
        for (int k = 0; k < 32; k++) z += sW3t[k * 32 + lane] * sU2[k];
        sZ[lane] = z;
        out[(size_t)NPTS * DIM + (size_t)row * 32 + lane] = z;
    }
    __syncwarp();
    {
        float h = __ldg(&d1[lane]);
#pragma unroll
        for (int k = 0; k < 32; k++) h += sD1t[k * 32 + lane] * sZ[k];
        sH1[lane] = fmaxf(h, 0.f);
    }
    __syncwarp();
#pragma unroll
    for (int hh = 0; hh < 2; hh++) {
        int o = lane + 32 * hh;
        float h = __ldg(&d2[o]);
#pragma unroll
        for (int k = 0; k < 32; k++) h += sD2t[k * 64 + o] * sH1[k];
        g_h2[(size_t)row * 64 + o] = fmaxf(h, 0.f);
    }
}

// ---------------- kernel DEC: x_hat = h2 @ D3^T + d3 ----------------
#define DEC_SMEM (2 * 64 * 132 * 4)
__global__ __launch_bounds__(256, 2) void dec_gemm(
    const float* __restrict__ D3, const float* __restrict__ d3,
    float* __restrict__ out) {
    extern __shared__ float ds[];
    float (*As)[132] = (float(*)[132])ds;
    float (*Bs)[132] = (float(*)[132])(ds + 64 * 132);
    const int tid = threadIdx.x;
    const int tx = tid & 15, ty = tid >> 4;
    const int row0 = blockIdx.x * 128;
    const int col0 = blockIdx.y * 128;

#pragma unroll
    for (int l = 0; l < 8; l++) {
        int e = tid + l * 256;
        int r = e >> 4, k4 = (e & 15) * 4;
        float4 va = *(const float4*)&g_h2[(size_t)(row0 + r) * 64 + k4];
        As[k4 + 0][r] = va.x; As[k4 + 1][r] = va.y; As[k4 + 2][r] = va.z; As[k4 + 3][r] = va.w;
        float4 vb = *(const float4*)&D3[(size_t)(col0 + r) * 64 + k4];
        Bs[k4 + 0][r] = vb.x; Bs[k4 + 1][r] = vb.y; Bs[k4 + 2][r] = vb.z; Bs[k4 + 3][r] = vb.w;
    }
    __syncthreads();

    float acc[8][8];
#pragma unroll
    for (int m = 0; m < 8; m++)
#pragma unroll
        for (int n = 0; n < 8; n++) acc[m][n] = 0.f;

#pragma unroll
    for (int k = 0; k < 64; k++) {
        float ar[8], br[8];
        float4 a0 = *(const float4*)&As[k][tx * 8];
        float4 a1 = *(const float4*)&As[k][tx * 8 + 4];
        ar[0] = a0.x; ar[1] = a0.y; ar[2] = a0.z; ar[3] = a0.w;
        ar[4] = a1.x; ar[5] = a1.y; ar[6] = a1.z; ar[7] = a1.w;
        float4 b0 = *(const float4*)&Bs[k][ty * 8];
        float4 b1 = *(const float4*)&Bs[k][ty * 8 + 4];
        br[0] = b0.x; br[1] = b0.y; br[2] = b0.z; br[3] = b0.w;
        br[4] = b1.x; br[5] = b1.y; br[6] = b1.z; br[7] = b1.w;
#pragma unroll
        for (int m = 0; m < 8; m++)
#pragma unroll
            for (int n = 0; n < 8; n++) acc[m][n] += ar[m] * br[n];
    }

#pragma unroll
    for (int m = 0; m < 8; m++) {
        int r = row0 + tx * 8 + m;
#pragma unroll
        for (int n = 0; n < 8; n++) {
            int cc = col0 + ty * 8 + n;
            out[(size_t)r * DIM + cc] = acc[m][n] + __ldg(&d3[cc]);
        }
    }
}

// ---------------- launch ----------------
extern "C" void kernel_launch(void* const* d_in, const int* in_sizes, int n_in,
                              void* d_out, int out_size) {
    const float* xs = (const float*)d_in[0];
    const float* W1 = (const float*)d_in[1];
    const float* b1 = (const float*)d_in[2];
    const float* W2 = (const float*)d_in[3];
    const float* b2 = (const float*)d_in[4];
    const float* W3 = (const float*)d_in[5];
    const float* b3 = (const float*)d_in[6];
    const float* D1 = (const float*)d_in[7];
    const float* d1 = (const float*)d_in[8];
    const float* D2 = (const float*)d_in[9];
    const float* d2 = (const float*)d_in[10];
    const float* D3 = (const float*)d_in[11];
    const float* d3 = (const float*)d_in[12];
    float* out = (float*)d_out;

    convert_norms_kernel<<<NPTS / 8, 256>>>(xs);

    cudaFuncSetAttribute(gram_store_tri, cudaFuncAttributeMaxDynamicSharedMemorySize, SMEM_GEMM);
    const int npairs = NBLK * (NBLK + 1) / 2;  // 2080
    gram_store_tri<<<npairs, 256, SMEM_GEMM>>>();

    scan_kernel<<<NPTS, 256>>>(xs);

    z1_gemm<<<NPTS / 64, 256>>>(xs, W1, b1);
    z2_kernel<<<NPTS / 8, 256>>>(W2, b2);
    pair_kernel<<<NPTS / 8, 256>>>(W2, b2, W3, b3, D1, d1, D2, d2, out);

    cudaFuncSetAttribute(dec_gemm, cudaFuncAttributeMaxDynamicSharedMemorySize, DEC_SMEM);
    dim3 gdec(NPTS / 128, 4);
    dec_gemm<<<gdec, 256, DEC_SMEM>>>(D3, d3, out);
}